// round 2
// baseline (speedup 1.0000x reference)
#include <cuda_runtime.h>
#include <cuda_bf16.h>
#include <math.h>

// Problem constants (shapes fixed by the dataset)
#define NN 50000
#define EE 800000
#define CC 128
#define HH 4
#define DD 32
#define QKV_COLS 384   // 3*C

// ---------------- device scratch (no allocations allowed) ----------------
__device__ float g_qkv[NN * QKV_COLS];          // 76.8 MB: [n][t*128 + h*32 + d]
__device__ int   g_offsets[NN + 1];             // CSR row offsets (by dst)
__device__ int   g_cursor[NN];                  // doubles as degree counter, then fill cursor
__device__ int   g_esrc[EE];                    // CSR: src index per slot
__device__ __align__(16) float g_rpeh[HH * 4];  // per-head {wx, wy, wz, b} (rpe collapsed over d)

// ---------------- 0) collapse RPE over d per head ----------------
__global__ void rpe_reduce_kernel(const float* __restrict__ rpe_w,
                                  const float* __restrict__ rpe_b) {
    int t = threadIdx.x;
    if (t >= HH * 4) return;
    int h = t >> 2, p = t & 3;
    float s = 0.f;
    for (int d = 0; d < DD; d++) {
        int r = h * DD + d;
        s += (p < 3) ? rpe_w[r * 3 + p] : rpe_b[r];
    }
    g_rpeh[t] = s;
}

// ---------------- 1) QKV GEMM: out[n][j] = bias[j] + sum_k feat[n][k]*W[j][k] ----------------
// A: [M,128] row-major, W: [384,128] row-major. Tile 64x64x16, 256 threads, 4x4 per thread.
#define BM 64
#define BN 64
#define BK 16
__global__ void gemm_qkv_kernel(const float* __restrict__ A,
                                const float* __restrict__ W,
                                const float* __restrict__ bias,
                                int M) {
    __shared__ float As[BK][BM + 4];
    __shared__ float Bs[BK][BN + 4];

    const int t  = threadIdx.x;          // 0..255
    const int tx = t & 15;               // 0..15 (n dir)
    const int ty = t >> 4;               // 0..15 (m dir)
    const int m0 = blockIdx.y * BM;
    const int n0 = blockIdx.x * BN;

    float acc[4][4];
#pragma unroll
    for (int i = 0; i < 4; i++)
#pragma unroll
        for (int j = 0; j < 4; j++) acc[i][j] = 0.f;

    for (int k0 = 0; k0 < CC; k0 += BK) {
#pragma unroll
        for (int i = 0; i < 4; i++) {
            int idx = t + i * 256;        // 0..1023
            int mm = idx >> 4;            // /BK
            int kk = idx & 15;            // %BK
            float av = 0.f;
            int gm = m0 + mm;
            if (gm < M) av = A[gm * CC + k0 + kk];
            As[kk][mm] = av;
            Bs[kk][mm] = W[(n0 + mm) * CC + k0 + kk];   // n0+mm always < 384
        }
        __syncthreads();

#pragma unroll
        for (int k = 0; k < BK; k++) {
            float a[4], b[4];
#pragma unroll
            for (int i = 0; i < 4; i++) a[i] = As[k][ty * 4 + i];
#pragma unroll
            for (int j = 0; j < 4; j++) b[j] = Bs[k][tx * 4 + j];
#pragma unroll
            for (int i = 0; i < 4; i++)
#pragma unroll
                for (int j = 0; j < 4; j++) acc[i][j] += a[i] * b[j];
        }
        __syncthreads();
    }

#pragma unroll
    for (int i = 0; i < 4; i++) {
        int m = m0 + ty * 4 + i;
        if (m >= M) continue;
#pragma unroll
        for (int j = 0; j < 4; j++) {
            int n = n0 + tx * 4 + j;
            g_qkv[m * QKV_COLS + n] = acc[i][j] + bias[n];
        }
    }
}

// ---------------- 2) CSR build ----------------
__global__ void zero_deg_kernel(int n) {
    int i = blockIdx.x * blockDim.x + threadIdx.x;
    if (i < n) g_cursor[i] = 0;
}

__global__ void count_kernel(const int* __restrict__ dst, int e) {
    int i = blockIdx.x * blockDim.x + threadIdx.x;
    if (i < e) atomicAdd(&g_cursor[dst[i]], 1);
}

// single-block exclusive scan: g_cursor (degrees) -> g_offsets
__global__ void scan_kernel(int n) {
    __shared__ int sh[1024];
    __shared__ int carry;
    if (threadIdx.x == 0) carry = 0;
    __syncthreads();
    for (int base = 0; base < n; base += 1024) {
        int i = base + (int)threadIdx.x;
        int v = (i < n) ? g_cursor[i] : 0;
        sh[threadIdx.x] = v;
        __syncthreads();
        for (int off = 1; off < 1024; off <<= 1) {
            int add = (threadIdx.x >= (unsigned)off) ? sh[threadIdx.x - off] : 0;
            __syncthreads();
            sh[threadIdx.x] += add;
            __syncthreads();
        }
        if (i < n) g_offsets[i] = carry + sh[threadIdx.x] - v;  // exclusive
        __syncthreads();
        if (threadIdx.x == 1023) carry += sh[1023];
        __syncthreads();
    }
    if (threadIdx.x == 0) g_offsets[n] = carry;
}

__global__ void copy_cursor_kernel(int n) {
    int i = blockIdx.x * blockDim.x + threadIdx.x;
    if (i < n) g_cursor[i] = g_offsets[i];
}

__global__ void fill_kernel(const int* __restrict__ dst,
                            const int* __restrict__ src, int e) {
    int i = blockIdx.x * blockDim.x + threadIdx.x;
    if (i < e) {
        int d = dst[i];
        int pos = atomicAdd(&g_cursor[d], 1);
        g_esrc[pos] = src[i];
    }
}

// ---------------- 3) fused per-node online-softmax attention ----------------
// One warp per node. Lane l: head h = l>>3, covers d = (l&7)*4 .. +3 (float4).
__global__ void attn_kernel(const float* __restrict__ coord,
                            float* __restrict__ out, int n) {
    int warp_in_block = threadIdx.x >> 5;
    int node = blockIdx.x * (blockDim.x >> 5) + warp_in_block;
    if (node >= n) return;
    int lane = threadIdx.x & 31;
    int h = lane >> 3;

    // per-head collapsed rpe coefficients
    float4 w = *reinterpret_cast<const float4*>(&g_rpeh[h * 4]);

    // query for this node (lane's 4 channels): q at qkv[node][0 + lane*4]
    const float4 q4 = *reinterpret_cast<const float4*>(&g_qkv[node * QKV_COLS + lane * 4]);

    float cdx = coord[node * 3 + 0];
    float cdy = coord[node * 3 + 1];
    float cdz = coord[node * 3 + 2];

    int beg = g_offsets[node];
    int end = g_offsets[node + 1];

    float m = -INFINITY;
    float lsum = 0.f;
    float4 acc = make_float4(0.f, 0.f, 0.f, 0.f);

    for (int i = beg; i < end; i++) {
        int src = g_esrc[i];
        const float4 k4 = *reinterpret_cast<const float4*>(&g_qkv[src * QKV_COLS + CC + lane * 4]);
        const float4 v4 = *reinterpret_cast<const float4*>(&g_qkv[src * QKV_COLS + 2 * CC + lane * 4]);

        float pd = q4.x * k4.x + q4.y * k4.y + q4.z * k4.z + q4.w * k4.w;
        pd += __shfl_xor_sync(0xffffffffu, pd, 1);
        pd += __shfl_xor_sync(0xffffffffu, pd, 2);
        pd += __shfl_xor_sync(0xffffffffu, pd, 4);
        // now pd = dot(q_h, k_h) for this lane's head (sum over 8 lanes * 4ch)

        float rx = cdx - coord[src * 3 + 0];
        float ry = cdy - coord[src * 3 + 1];
        float rz = cdz - coord[src * 3 + 2];
        float logit = pd + rx * w.x + ry * w.y + rz * w.z + w.w;

        float mn = fmaxf(m, logit);
        float sc = __expf(m - mn);       // 0 on first iter (m=-inf)
        float p  = __expf(logit - mn);
        lsum = lsum * sc + p;
        acc.x = acc.x * sc + p * v4.x;
        acc.y = acc.y * sc + p * v4.y;
        acc.z = acc.z * sc + p * v4.z;
        acc.w = acc.w * sc + p * v4.w;
        m = mn;
    }

    float inv = (lsum > 0.f) ? (1.f / lsum) : 0.f;
    float4 r = make_float4(acc.x * inv, acc.y * inv, acc.z * inv, acc.w * inv);
    *reinterpret_cast<float4*>(&out[node * CC + lane * 4]) = r;
}

// ---------------- launch ----------------
extern "C" void kernel_launch(void* const* d_in, const int* in_sizes, int n_in,
                              void* d_out, int out_size) {
    const float* feat   = (const float*)d_in[0];
    const float* coord  = (const float*)d_in[1];
    const int*   graph  = (const int*)d_in[2];
    const float* qkv_w  = (const float*)d_in[3];
    const float* qkv_b  = (const float*)d_in[4];
    const float* rpe_w  = (const float*)d_in[5];
    const float* rpe_b  = (const float*)d_in[6];
    float* out = (float*)d_out;

    int n = in_sizes[0] / CC;      // 50000
    int e = in_sizes[2] / 2;       // 800000
    if (n > NN) n = NN;
    if (e > EE) e = EE;

    const int* dst = graph;
    const int* src = graph + e;

    // 0) rpe collapse
    rpe_reduce_kernel<<<1, 32>>>(rpe_w, rpe_b);

    // 1) QKV gemm
    {
        dim3 grid(QKV_COLS / BN, (n + BM - 1) / BM);
        gemm_qkv_kernel<<<grid, 256>>>(feat, qkv_w, qkv_b, n);
    }

    // 2) CSR build by dst
    {
        int tb = 256;
        zero_deg_kernel<<<(n + tb - 1) / tb, tb>>>(n);
        count_kernel<<<(e + tb - 1) / tb, tb>>>(dst, e);
        scan_kernel<<<1, 1024>>>(n);
        copy_cursor_kernel<<<(n + tb - 1) / tb, tb>>>(n);
        fill_kernel<<<(e + tb - 1) / tb, tb>>>(dst, src, e);
    }

    // 3) fused attention (1 warp / node)
    {
        int warps_per_block = 8;
        int tb = warps_per_block * 32;
        int grid = (n + warps_per_block - 1) / warps_per_block;
        attn_kernel<<<grid, tb>>>(coord, out, n);
    }
}

// round 4
// speedup vs baseline: 1.4788x; 1.4788x over previous
#include <cuda_runtime.h>
#include <cuda_bf16.h>
#include <math.h>

// Problem constants (shapes fixed by the dataset)
#define NN 50000
#define EE 800000
#define CC 128
#define HH 4
#define DD 32
#define QKV_COLS 384   // 3*C

#define SCAN_CHUNK 1024
#define NB_SCAN ((NN + SCAN_CHUNK - 1) / SCAN_CHUNK)   // 49

// ---------------- device scratch (no allocations allowed) ----------------
__device__ float g_qkv[NN * QKV_COLS];          // 76.8 MB: [n][t*128 + h*32 + d]
__device__ int   g_offsets[NN + 1];             // CSR row offsets (by dst)
__device__ int   g_cursor[NN];                  // degree counter, then fill cursor
__device__ int   g_esrc[EE];                    // CSR: src index per slot
__device__ int   g_bsum[NB_SCAN + 1];           // per-block sums for scan
__device__ __align__(16) float g_rpeh[HH * 4];  // per-head {wx, wy, wz, b}

// ---------------- 0) collapse RPE over d per head + zero degree counters ----------------
__global__ void init_kernel(const float* __restrict__ rpe_w,
                            const float* __restrict__ rpe_b, int n) {
    int i = blockIdx.x * blockDim.x + threadIdx.x;
    if (i < n) g_cursor[i] = 0;
    if (blockIdx.x == 0 && threadIdx.x < HH * 4) {
        int t = threadIdx.x;
        int h = t >> 2, p = t & 3;
        float s = 0.f;
        for (int d = 0; d < DD; d++) {
            int r = h * DD + d;
            s += (p < 3) ? rpe_w[r * 3 + p] : rpe_b[r];
        }
        g_rpeh[t] = s;
    }
}

// ---------------- 1) QKV GEMM: 128x128x16 tile, 256 thr, 8x8 per thread ----------------
#define GBM 128
#define GBN 128
#define GBK 16
__global__ __launch_bounds__(256, 2)
void gemm_qkv_kernel(const float* __restrict__ A,
                     const float* __restrict__ W,
                     const float* __restrict__ bias,
                     int M) {
    __shared__ float As[GBK][GBM + 4];
    __shared__ float Bs[GBK][GBN + 4];

    const int t  = threadIdx.x;          // 0..255
    const int tx = t & 15;               // n-dir thread col (8 each)
    const int ty = t >> 4;               // m-dir thread row (8 each)
    const int m0 = blockIdx.y * GBM;
    const int n0 = blockIdx.x * GBN;

    float acc[8][8];
#pragma unroll
    for (int i = 0; i < 8; i++)
#pragma unroll
        for (int j = 0; j < 8; j++) acc[i][j] = 0.f;

    for (int k0 = 0; k0 < CC; k0 += GBK) {
        // load 128 rows x 16 cols of A and W, as float4, transposed into [k][m]
#pragma unroll
        for (int u = 0; u < 2; u++) {
            int idx = t + u * 256;        // 0..511
            int row = idx >> 2;           // 0..127
            int c4  = (idx & 3) * 4;      // 0,4,8,12
            float4 av = make_float4(0.f, 0.f, 0.f, 0.f);
            int gm = m0 + row;
            if (gm < M) av = *reinterpret_cast<const float4*>(&A[gm * CC + k0 + c4]);
            As[c4 + 0][row] = av.x;
            As[c4 + 1][row] = av.y;
            As[c4 + 2][row] = av.z;
            As[c4 + 3][row] = av.w;
            float4 bv = *reinterpret_cast<const float4*>(&W[(n0 + row) * CC + k0 + c4]);
            Bs[c4 + 0][row] = bv.x;
            Bs[c4 + 1][row] = bv.y;
            Bs[c4 + 2][row] = bv.z;
            Bs[c4 + 3][row] = bv.w;
        }
        __syncthreads();

#pragma unroll
        for (int k = 0; k < GBK; k++) {
            float4 a0 = *reinterpret_cast<const float4*>(&As[k][ty * 8]);
            float4 a1 = *reinterpret_cast<const float4*>(&As[k][ty * 8 + 4]);
            float4 b0 = *reinterpret_cast<const float4*>(&Bs[k][tx * 8]);
            float4 b1 = *reinterpret_cast<const float4*>(&Bs[k][tx * 8 + 4]);
            float a[8] = {a0.x, a0.y, a0.z, a0.w, a1.x, a1.y, a1.z, a1.w};
            float b[8] = {b0.x, b0.y, b0.z, b0.w, b1.x, b1.y, b1.z, b1.w};
#pragma unroll
            for (int i = 0; i < 8; i++)
#pragma unroll
                for (int j = 0; j < 8; j++) acc[i][j] += a[i] * b[j];
        }
        __syncthreads();
    }

    // epilogue: add bias, store (vectorized)
    float bv[8];
#pragma unroll
    for (int j = 0; j < 8; j++) bv[j] = bias[n0 + tx * 8 + j];
#pragma unroll
    for (int i = 0; i < 8; i++) {
        int m = m0 + ty * 8 + i;
        if (m >= M) continue;
        float4 r0 = make_float4(acc[i][0] + bv[0], acc[i][1] + bv[1],
                                acc[i][2] + bv[2], acc[i][3] + bv[3]);
        float4 r1 = make_float4(acc[i][4] + bv[4], acc[i][5] + bv[5],
                                acc[i][6] + bv[6], acc[i][7] + bv[7]);
        float* dst = &g_qkv[m * QKV_COLS + n0 + tx * 8];
        *reinterpret_cast<float4*>(dst)     = r0;
        *reinterpret_cast<float4*>(dst + 4) = r1;
    }
}

// ---------------- 2) CSR build ----------------
__global__ void count_kernel(const int* __restrict__ dst, int e) {
    int i = blockIdx.x * blockDim.x + threadIdx.x;
    if (i < e) atomicAdd(&g_cursor[dst[i]], 1);
}

// warp-shuffle block scan: 1024-elem chunk per block
__device__ __forceinline__ int block_scan_inclusive(int v, int* warp_sums) {
    int lane = threadIdx.x & 31;
    int wid  = threadIdx.x >> 5;
    int x = v;
#pragma unroll
    for (int off = 1; off < 32; off <<= 1) {
        int y = __shfl_up_sync(0xffffffffu, x, off);
        if (lane >= off) x += y;
    }
    if (lane == 31) warp_sums[wid] = x;
    __syncthreads();
    if (wid == 0) {
        int ws = warp_sums[lane];
#pragma unroll
        for (int off = 1; off < 32; off <<= 1) {
            int y = __shfl_up_sync(0xffffffffu, ws, off);
            if (lane >= off) ws += y;
        }
        warp_sums[lane] = ws;
    }
    __syncthreads();
    int base = (wid > 0) ? warp_sums[wid - 1] : 0;
    return base + x;   // inclusive
}

__global__ void scan1_kernel(int n) {          // grid = NB_SCAN, block = 1024
    __shared__ int warp_sums[32];
    int i = blockIdx.x * SCAN_CHUNK + threadIdx.x;
    int v = (i < n) ? g_cursor[i] : 0;
    int inc = block_scan_inclusive(v, warp_sums);
    if (i < n) g_offsets[i] = inc - v;          // local exclusive
    if (threadIdx.x == SCAN_CHUNK - 1) g_bsum[blockIdx.x] = inc;
}

__global__ void scan2_kernel(int nb) {         // 1 block, 1024 threads
    __shared__ int warp_sums[32];
    int v = (threadIdx.x < (unsigned)nb) ? g_bsum[threadIdx.x] : 0;
    int inc = block_scan_inclusive(v, warp_sums);
    if (threadIdx.x < (unsigned)nb) g_bsum[threadIdx.x] = inc - v;   // exclusive
}

__global__ void scan3_kernel(int n, int e) {   // grid = NB_SCAN, block = 1024
    int i = blockIdx.x * SCAN_CHUNK + threadIdx.x;
    if (i < n) {
        int off = g_offsets[i] + g_bsum[blockIdx.x];
        g_offsets[i] = off;
        g_cursor[i]  = off;
    }
    if (i == 0) g_offsets[n] = e;
}

__global__ void fill_kernel(const int* __restrict__ dst,
                            const int* __restrict__ src, int e) {
    int i = blockIdx.x * blockDim.x + threadIdx.x;
    if (i < e) {
        int d = dst[i];
        int pos = atomicAdd(&g_cursor[d], 1);
        g_esrc[pos] = src[i];
    }
}

// ---------------- 3) fused per-node online-softmax attention ----------------
// One warp per node. Lane l: head h = l>>3, covers d = (l&7)*4 .. +3 (float4).
__global__ void attn_kernel(const float* __restrict__ coord,
                            float* __restrict__ out, int n) {
    int warp_in_block = threadIdx.x >> 5;
    int node = blockIdx.x * (blockDim.x >> 5) + warp_in_block;
    if (node >= n) return;
    int lane = threadIdx.x & 31;
    int h = lane >> 3;

    float4 w = *reinterpret_cast<const float4*>(&g_rpeh[h * 4]);
    const float4 q4 = *reinterpret_cast<const float4*>(&g_qkv[node * QKV_COLS + lane * 4]);

    float cdx = coord[node * 3 + 0];
    float cdy = coord[node * 3 + 1];
    float cdz = coord[node * 3 + 2];

    int beg = g_offsets[node];
    int end = g_offsets[node + 1];

    float m = -INFINITY;
    float lsum = 0.f;
    float4 acc = make_float4(0.f, 0.f, 0.f, 0.f);

    int i = beg;
    for (; i + 1 < end; i += 2) {
        int s0 = g_esrc[i];
        int s1 = g_esrc[i + 1];
        const float4 k0 = *reinterpret_cast<const float4*>(&g_qkv[s0 * QKV_COLS + CC + lane * 4]);
        const float4 v0 = *reinterpret_cast<const float4*>(&g_qkv[s0 * QKV_COLS + 2 * CC + lane * 4]);
        const float4 k1 = *reinterpret_cast<const float4*>(&g_qkv[s1 * QKV_COLS + CC + lane * 4]);
        const float4 v1 = *reinterpret_cast<const float4*>(&g_qkv[s1 * QKV_COLS + 2 * CC + lane * 4]);

        float r0x = cdx - coord[s0 * 3 + 0];
        float r0y = cdy - coord[s0 * 3 + 1];
        float r0z = cdz - coord[s0 * 3 + 2];
        float r1x = cdx - coord[s1 * 3 + 0];
        float r1y = cdy - coord[s1 * 3 + 1];
        float r1z = cdz - coord[s1 * 3 + 2];

        float p0 = q4.x * k0.x + q4.y * k0.y + q4.z * k0.z + q4.w * k0.w;
        float p1 = q4.x * k1.x + q4.y * k1.y + q4.z * k1.z + q4.w * k1.w;
        p0 += __shfl_xor_sync(0xffffffffu, p0, 1);
        p1 += __shfl_xor_sync(0xffffffffu, p1, 1);
        p0 += __shfl_xor_sync(0xffffffffu, p0, 2);
        p1 += __shfl_xor_sync(0xffffffffu, p1, 2);
        p0 += __shfl_xor_sync(0xffffffffu, p0, 4);
        p1 += __shfl_xor_sync(0xffffffffu, p1, 4);

        float l0 = p0 + r0x * w.x + r0y * w.y + r0z * w.z + w.w;
        float l1 = p1 + r1x * w.x + r1y * w.y + r1z * w.z + w.w;

        float mn = fmaxf(m, fmaxf(l0, l1));
        float sc = __expf(m - mn);
        float e0 = __expf(l0 - mn);
        float e1 = __expf(l1 - mn);
        lsum = lsum * sc + e0 + e1;
        acc.x = acc.x * sc + e0 * v0.x + e1 * v1.x;
        acc.y = acc.y * sc + e0 * v0.y + e1 * v1.y;
        acc.z = acc.z * sc + e0 * v0.z + e1 * v1.z;
        acc.w = acc.w * sc + e0 * v0.w + e1 * v1.w;
        m = mn;
    }
    if (i < end) {
        int s0 = g_esrc[i];
        const float4 k0 = *reinterpret_cast<const float4*>(&g_qkv[s0 * QKV_COLS + CC + lane * 4]);
        const float4 v0 = *reinterpret_cast<const float4*>(&g_qkv[s0 * QKV_COLS + 2 * CC + lane * 4]);
        float rx = cdx - coord[s0 * 3 + 0];
        float ry = cdy - coord[s0 * 3 + 1];
        float rz = cdz - coord[s0 * 3 + 2];
        float p0 = q4.x * k0.x + q4.y * k0.y + q4.z * k0.z + q4.w * k0.w;
        p0 += __shfl_xor_sync(0xffffffffu, p0, 1);
        p0 += __shfl_xor_sync(0xffffffffu, p0, 2);
        p0 += __shfl_xor_sync(0xffffffffu, p0, 4);
        float l0 = p0 + rx * w.x + ry * w.y + rz * w.z + w.w;
        float mn = fmaxf(m, l0);
        float sc = __expf(m - mn);
        float e0 = __expf(l0 - mn);
        lsum = lsum * sc + e0;
        acc.x = acc.x * sc + e0 * v0.x;
        acc.y = acc.y * sc + e0 * v0.y;
        acc.z = acc.z * sc + e0 * v0.z;
        acc.w = acc.w * sc + e0 * v0.w;
        m = mn;
    }

    float inv = (lsum > 0.f) ? (1.f / lsum) : 0.f;
    float4 r = make_float4(acc.x * inv, acc.y * inv, acc.z * inv, acc.w * inv);
    *reinterpret_cast<float4*>(&out[node * CC + lane * 4]) = r;
}

// ---------------- launch ----------------
extern "C" void kernel_launch(void* const* d_in, const int* in_sizes, int n_in,
                              void* d_out, int out_size) {
    const float* feat   = (const float*)d_in[0];
    const float* coord  = (const float*)d_in[1];
    const int*   graph  = (const int*)d_in[2];
    const float* qkv_w  = (const float*)d_in[3];
    const float* qkv_b  = (const float*)d_in[4];
    const float* rpe_w  = (const float*)d_in[5];
    const float* rpe_b  = (const float*)d_in[6];
    float* out = (float*)d_out;

    int n = in_sizes[0] / CC;      // 50000
    int e = in_sizes[2] / 2;       // 800000
    if (n > NN) n = NN;
    if (e > EE) e = EE;

    const int* dst = graph;
    const int* src = graph + e;

    // 0) init: zero degrees + rpe collapse
    init_kernel<<<(n + 255) / 256, 256>>>(rpe_w, rpe_b, n);

    // 1) QKV gemm
    {
        dim3 grid(QKV_COLS / GBN, (n + GBM - 1) / GBM);
        gemm_qkv_kernel<<<grid, 256>>>(feat, qkv_w, qkv_b, n);
    }

    // 2) CSR build by dst
    {
        int tb = 256;
        count_kernel<<<(e + tb - 1) / tb, tb>>>(dst, e);
        int nb = (n + SCAN_CHUNK - 1) / SCAN_CHUNK;
        scan1_kernel<<<nb, SCAN_CHUNK>>>(n);
        scan2_kernel<<<1, SCAN_CHUNK>>>(nb);
        scan3_kernel<<<nb, SCAN_CHUNK>>>(n, e);
        fill_kernel<<<(e + tb - 1) / tb, tb>>>(dst, src, e);
    }

    // 3) fused attention (1 warp / node)
    {
        int warps_per_block = 8;
        int tb = warps_per_block * 32;
        int grid = (n + warps_per_block - 1) / warps_per_block;
        attn_kernel<<<grid, tb>>>(coord, out, n);
    }
}

// round 7
// speedup vs baseline: 1.7476x; 1.1818x over previous
#include <cuda_runtime.h>
#include <cuda_bf16.h>
#include <math.h>
#include <stdint.h>

// Problem constants (shapes fixed by the dataset)
#define NN 50000
#define EE 800000
#define CC 128
#define HH 4
#define DD 32
#define QKV_COLS 384   // 3*C

#define SCAN_CHUNK 1024
#define NB_SCAN ((NN + SCAN_CHUNK - 1) / SCAN_CHUNK)   // 49

// GEMM config: D[M,384] = Avirt[M,384] @ Bvirt[384,384]^T where
// Avirt = [a_hi | a_lo | a_hi], Bvirt = [b_hi | b_hi | b_lo]  (3-term bf16 split).
// Physically staged: A = [hi|lo] 256, B = [hi|lo] 256; segments remapped in k-loop.
#define KC 256
#define TM 128
#define TN 128
#define SM_A 0
#define SM_B (TM * KC * 2)              // 65536
#define SM_TOT (SM_B + TN * KC * 2)    // 131072

// ---------------- device scratch (no allocations allowed) ----------------
__device__ float g_qkv[NN * QKV_COLS];                       // 76.8 MB
__device__ __align__(16) __nv_bfloat16 g_a16[NN * KC];       // 25.6 MB  [m][hi(128)|lo(128)]
__device__ __align__(16) __nv_bfloat16 g_b16[QKV_COLS * KC]; // 0.2 MB   [n][hi|lo]
__device__ int   g_offsets[NN + 1];
__device__ int   g_cursor[NN];
__device__ int   g_esrc[EE];
__device__ int   g_bsum[NB_SCAN + 1];
__device__ __align__(16) float g_rpeh[HH * 4];

__device__ __forceinline__ uint32_t smem_to_u32(const void* p) {
    uint32_t a;
    asm("{ .reg .u64 t; cvta.to.shared.u64 t, %1; cvt.u32.u64 %0, t; }" : "=r"(a) : "l"(p));
    return a;
}
#define LDMATRIX_X4(r0, r1, r2, r3, addr) \
    asm volatile("ldmatrix.sync.aligned.m8n8.x4.shared.b16 {%0,%1,%2,%3}, [%4];" \
                 : "=r"(r0), "=r"(r1), "=r"(r2), "=r"(r3) : "r"(addr))
#define MMA_BF16(d, a, b0, b1) \
    asm volatile("mma.sync.aligned.m16n8k16.row.col.f32.bf16.bf16.f32 " \
                 "{%0,%1,%2,%3}, {%4,%5,%6,%7}, {%8,%9}, {%0,%1,%2,%3};" \
                 : "+f"((d)[0]), "+f"((d)[1]), "+f"((d)[2]), "+f"((d)[3]) \
                 : "r"((a)[0]), "r"((a)[1]), "r"((a)[2]), "r"((a)[3]), \
                   "r"(b0), "r"(b1))

// ---------------- 0) init: rpe collapse + zero degree counters ----------------
__global__ void init_kernel(const float* __restrict__ rpe_w,
                            const float* __restrict__ rpe_b, int n) {
    int i = blockIdx.x * blockDim.x + threadIdx.x;
    if (i < n) g_cursor[i] = 0;
    if (blockIdx.x == 0 && threadIdx.x < HH * 4) {
        int t = threadIdx.x;
        int h = t >> 2, p = t & 3;
        float s = 0.f;
        for (int d = 0; d < DD; d++) {
            int r = h * DD + d;
            s += (p < 3) ? rpe_w[r * 3 + p] : rpe_b[r];
        }
        g_rpeh[t] = s;
    }
}

// ---------------- 0b) fp32 -> bf16 hi/lo split ----------------
__global__ void conv_a_kernel(const float* __restrict__ feat, int n) {
    int idx = blockIdx.x * blockDim.x + threadIdx.x;
    if (idx >= n * CC) return;
    int m = idx >> 7, k = idx & 127;
    float x = feat[idx];
    __nv_bfloat16 h = __float2bfloat16(x);
    __nv_bfloat16 l = __float2bfloat16(x - __bfloat162float(h));
    g_a16[m * KC + k] = h;
    g_a16[m * KC + CC + k] = l;
}
__global__ void conv_b_kernel(const float* __restrict__ w) {
    int idx = blockIdx.x * blockDim.x + threadIdx.x;
    if (idx >= QKV_COLS * CC) return;
    int m = idx >> 7, k = idx & 127;
    float x = w[idx];
    __nv_bfloat16 h = __float2bfloat16(x);
    __nv_bfloat16 l = __float2bfloat16(x - __bfloat162float(h));
    g_b16[m * KC + k] = h;
    g_b16[m * KC + CC + k] = l;
}

// ---------------- 1) mma.sync bf16 3-term split GEMM ----------------
// grid (3, ceil(M/128)), 256 threads = 8 warps, warp tile 64x32.
// 24 k16 steps: ks 0-7 -> ah*bh, ks 8-15 -> al*bh, ks 16-23 -> ah*bl.
__global__ __launch_bounds__(256)
void mma_gemm_kernel(const float* __restrict__ bias, int M) {
    extern __shared__ char smem[];
    const uint32_t smA = smem_to_u32(smem) + SM_A;
    const uint32_t smB = smem_to_u32(smem) + SM_B;
    const int tid = threadIdx.x;
    const int lane = tid & 31;
    const int wid = tid >> 5;
    const int warpM = wid >> 2;   // 0..1  (64 rows each)
    const int warpN = wid & 3;    // 0..3  (32 cols each)
    const int m0 = blockIdx.y * TM;
    const int n0 = blockIdx.x * TN;

    // ---- stage A,B tiles (XOR-swizzled 16B chunks; 32 chunks per 512B row) ----
    {
        const uint4* a4 = reinterpret_cast<const uint4*>(g_a16);
        const uint4* b4 = reinterpret_cast<const uint4*>(g_b16);
        const uint4 z4 = make_uint4(0u, 0u, 0u, 0u);
#pragma unroll
        for (int i = 0; i < 16; i++) {
            int idx = tid + i * 256;      // 0..4095
            int row = idx >> 5;           // 0..127
            int c   = idx & 31;           // 16B chunk along k
            uint32_t off = (uint32_t)row * 512u + (uint32_t)((c ^ (row & 7)) << 4);
            int gm = m0 + row;
            uint4 av = (gm < M) ? a4[(size_t)gm * 32 + c] : z4;
            *reinterpret_cast<uint4*>((char*)smem + SM_A + off) = av;
            uint4 bv = b4[(size_t)(n0 + row) * 32 + c];
            *reinterpret_cast<uint4*>((char*)smem + SM_B + off) = bv;
        }
    }
    __syncthreads();

    float acc[4][4][4];
#pragma unroll
    for (int mt = 0; mt < 4; mt++)
#pragma unroll
        for (int nt = 0; nt < 4; nt++)
#pragma unroll
            for (int c = 0; c < 4; c++) acc[mt][nt][c] = 0.f;

    const int arow_base = warpM * 64 + (lane & 15);
    const int brow_base = warpN * 32 + (lane & 15);
    const int chalf = lane >> 4;    // 0 or 1: which 16B chunk of the k16 step

#pragma unroll 4
    for (int ks = 0; ks < 24; ks++) {
        // virtual K=384 segment remap onto the physical [hi|lo] tiles:
        //   A: [ah (k16 0-7) | al (8-15) | ah (16-23 -> 0-7)]
        //   B: [bh (0-7)     | bh (8-15 -> 0-7) | bl (16-23 -> 8-15)]
        int aj = (ks < 16) ? ks : ks - 16;
        int bj = (ks < 8)  ? ks : ks - 8;
        uint32_t af[4][4];
#pragma unroll
        for (int mt = 0; mt < 4; mt++) {
            int r = arow_base + mt * 16;
            int c = aj * 2 + chalf;
            uint32_t addr = smA + (uint32_t)r * 512u + (uint32_t)((c ^ (r & 7)) << 4);
            LDMATRIX_X4(af[mt][0], af[mt][1], af[mt][2], af[mt][3], addr);
        }
        uint32_t bf[2][4];
#pragma unroll
        for (int bt = 0; bt < 2; bt++) {
            int r = brow_base + bt * 16;
            int c = bj * 2 + chalf;
            uint32_t addr = smB + (uint32_t)r * 512u + (uint32_t)((c ^ (r & 7)) << 4);
            LDMATRIX_X4(bf[bt][0], bf[bt][1], bf[bt][2], bf[bt][3], addr);
        }
#pragma unroll
        for (int mt = 0; mt < 4; mt++)
#pragma unroll
            for (int nt = 0; nt < 4; nt++) {
                int bt = nt >> 1, sub = nt & 1;
                // fragment pairs: n-subtile 0 -> {r0,r2}, subtile 1 -> {r1,r3}
                MMA_BF16(acc[mt][nt], af[mt], bf[bt][sub], bf[bt][sub + 2]);
            }
    }

    // ---- epilogue: add bias, store float2 pairs ----
    const int groupID = lane >> 2;
    const int tq = lane & 3;
#pragma unroll
    for (int mt = 0; mt < 4; mt++) {
#pragma unroll
        for (int nt = 0; nt < 4; nt++) {
            int col = n0 + warpN * 32 + nt * 8 + tq * 2;
            float2 b = *reinterpret_cast<const float2*>(&bias[col]);
            int r0 = m0 + warpM * 64 + mt * 16 + groupID;
            if (r0 < M) {
                float2 o = make_float2(acc[mt][nt][0] + b.x, acc[mt][nt][1] + b.y);
                *reinterpret_cast<float2*>(&g_qkv[(size_t)r0 * QKV_COLS + col]) = o;
            }
            int r1 = r0 + 8;
            if (r1 < M) {
                float2 o = make_float2(acc[mt][nt][2] + b.x, acc[mt][nt][3] + b.y);
                *reinterpret_cast<float2*>(&g_qkv[(size_t)r1 * QKV_COLS + col]) = o;
            }
        }
    }
}

// ---------------- 2) CSR build ----------------
__global__ void count_kernel(const int* __restrict__ dst, int e) {
    int i = blockIdx.x * blockDim.x + threadIdx.x;
    if (i < e) atomicAdd(&g_cursor[dst[i]], 1);
}

__device__ __forceinline__ int block_scan_inclusive(int v, int* warp_sums) {
    int lane = threadIdx.x & 31;
    int wid  = threadIdx.x >> 5;
    int x = v;
#pragma unroll
    for (int off = 1; off < 32; off <<= 1) {
        int y = __shfl_up_sync(0xffffffffu, x, off);
        if (lane >= off) x += y;
    }
    if (lane == 31) warp_sums[wid] = x;
    __syncthreads();
    if (wid == 0) {
        int ws = warp_sums[lane];
#pragma unroll
        for (int off = 1; off < 32; off <<= 1) {
            int y = __shfl_up_sync(0xffffffffu, ws, off);
            if (lane >= off) ws += y;
        }
        warp_sums[lane] = ws;
    }
    __syncthreads();
    int base = (wid > 0) ? warp_sums[wid - 1] : 0;
    return base + x;
}

__global__ void scan1_kernel(int n) {
    __shared__ int warp_sums[32];
    int i = blockIdx.x * SCAN_CHUNK + threadIdx.x;
    int v = (i < n) ? g_cursor[i] : 0;
    int inc = block_scan_inclusive(v, warp_sums);
    if (i < n) g_offsets[i] = inc - v;
    if (threadIdx.x == SCAN_CHUNK - 1) g_bsum[blockIdx.x] = inc;
}
__global__ void scan2_kernel(int nb) {
    __shared__ int warp_sums[32];
    int v = (threadIdx.x < (unsigned)nb) ? g_bsum[threadIdx.x] : 0;
    int inc = block_scan_inclusive(v, warp_sums);
    if (threadIdx.x < (unsigned)nb) g_bsum[threadIdx.x] = inc - v;
}
__global__ void scan3_kernel(int n, int e) {
    int i = blockIdx.x * SCAN_CHUNK + threadIdx.x;
    if (i < n) {
        int off = g_offsets[i] + g_bsum[blockIdx.x];
        g_offsets[i] = off;
        g_cursor[i]  = off;
    }
    if (i == 0) g_offsets[n] = e;
}
__global__ void fill_kernel(const int* __restrict__ dst,
                            const int* __restrict__ src, int e) {
    int i = blockIdx.x * blockDim.x + threadIdx.x;
    if (i < e) {
        int d = dst[i];
        int pos = atomicAdd(&g_cursor[d], 1);
        g_esrc[pos] = src[i];
    }
}

// ---------------- 3) fused per-node online-softmax attention ----------------
__global__ void attn_kernel(const float* __restrict__ coord,
                            float* __restrict__ out, int n) {
    int warp_in_block = threadIdx.x >> 5;
    int node = blockIdx.x * (blockDim.x >> 5) + warp_in_block;
    if (node >= n) return;
    int lane = threadIdx.x & 31;
    int h = lane >> 3;

    float4 w = *reinterpret_cast<const float4*>(&g_rpeh[h * 4]);
    const float4 q4 = *reinterpret_cast<const float4*>(&g_qkv[node * QKV_COLS + lane * 4]);

    float cdx = coord[node * 3 + 0];
    float cdy = coord[node * 3 + 1];
    float cdz = coord[node * 3 + 2];

    int beg = g_offsets[node];
    int end = g_offsets[node + 1];

    float m = -INFINITY;
    float lsum = 0.f;
    float4 acc = make_float4(0.f, 0.f, 0.f, 0.f);

    int i = beg;
    for (; i + 1 < end; i += 2) {
        int s0 = g_esrc[i];
        int s1 = g_esrc[i + 1];
        const float4 k0 = *reinterpret_cast<const float4*>(&g_qkv[s0 * QKV_COLS + CC + lane * 4]);
        const float4 v0 = *reinterpret_cast<const float4*>(&g_qkv[s0 * QKV_COLS + 2 * CC + lane * 4]);
        const float4 k1 = *reinterpret_cast<const float4*>(&g_qkv[s1 * QKV_COLS + CC + lane * 4]);
        const float4 v1 = *reinterpret_cast<const float4*>(&g_qkv[s1 * QKV_COLS + 2 * CC + lane * 4]);

        float r0x = cdx - coord[s0 * 3 + 0];
        float r0y = cdy - coord[s0 * 3 + 1];
        float r0z = cdz - coord[s0 * 3 + 2];
        float r1x = cdx - coord[s1 * 3 + 0];
        float r1y = cdy - coord[s1 * 3 + 1];
        float r1z = cdz - coord[s1 * 3 + 2];

        float p0 = q4.x * k0.x + q4.y * k0.y + q4.z * k0.z + q4.w * k0.w;
        float p1 = q4.x * k1.x + q4.y * k1.y + q4.z * k1.z + q4.w * k1.w;
        p0 += __shfl_xor_sync(0xffffffffu, p0, 1);
        p1 += __shfl_xor_sync(0xffffffffu, p1, 1);
        p0 += __shfl_xor_sync(0xffffffffu, p0, 2);
        p1 += __shfl_xor_sync(0xffffffffu, p1, 2);
        p0 += __shfl_xor_sync(0xffffffffu, p0, 4);
        p1 += __shfl_xor_sync(0xffffffffu, p1, 4);

        float l0 = p0 + r0x * w.x + r0y * w.y + r0z * w.z + w.w;
        float l1 = p1 + r1x * w.x + r1y * w.y + r1z * w.z + w.w;

        float mn = fmaxf(m, fmaxf(l0, l1));
        float sc = __expf(m - mn);
        float e0 = __expf(l0 - mn);
        float e1 = __expf(l1 - mn);
        lsum = lsum * sc + e0 + e1;
        acc.x = acc.x * sc + e0 * v0.x + e1 * v1.x;
        acc.y = acc.y * sc + e0 * v0.y + e1 * v1.y;
        acc.z = acc.z * sc + e0 * v0.z + e1 * v1.z;
        acc.w = acc.w * sc + e0 * v0.w + e1 * v1.w;
        m = mn;
    }
    if (i < end) {
        int s0 = g_esrc[i];
        const float4 k0 = *reinterpret_cast<const float4*>(&g_qkv[s0 * QKV_COLS + CC + lane * 4]);
        const float4 v0 = *reinterpret_cast<const float4*>(&g_qkv[s0 * QKV_COLS + 2 * CC + lane * 4]);
        float rx = cdx - coord[s0 * 3 + 0];
        float ry = cdy - coord[s0 * 3 + 1];
        float rz = cdz - coord[s0 * 3 + 2];
        float p0 = q4.x * k0.x + q4.y * k0.y + q4.z * k0.z + q4.w * k0.w;
        p0 += __shfl_xor_sync(0xffffffffu, p0, 1);
        p0 += __shfl_xor_sync(0xffffffffu, p0, 2);
        p0 += __shfl_xor_sync(0xffffffffu, p0, 4);
        float l0 = p0 + rx * w.x + ry * w.y + rz * w.z + w.w;
        float mn = fmaxf(m, l0);
        float sc = __expf(m - mn);
        float e0 = __expf(l0 - mn);
        lsum = lsum * sc + e0;
        acc.x = acc.x * sc + e0 * v0.x;
        acc.y = acc.y * sc + e0 * v0.y;
        acc.z = acc.z * sc + e0 * v0.z;
        acc.w = acc.w * sc + e0 * v0.w;
        m = mn;
    }

    float inv = (lsum > 0.f) ? (1.f / lsum) : 0.f;
    float4 r = make_float4(acc.x * inv, acc.y * inv, acc.z * inv, acc.w * inv);
    *reinterpret_cast<float4*>(&out[node * CC + lane * 4]) = r;
}

// ---------------- launch ----------------
extern "C" void kernel_launch(void* const* d_in, const int* in_sizes, int n_in,
                              void* d_out, int out_size) {
    const float* feat   = (const float*)d_in[0];
    const float* coord  = (const float*)d_in[1];
    const int*   graph  = (const int*)d_in[2];
    const float* qkv_w  = (const float*)d_in[3];
    const float* qkv_b  = (const float*)d_in[4];
    const float* rpe_w  = (const float*)d_in[5];
    const float* rpe_b  = (const float*)d_in[6];
    float* out = (float*)d_out;

    int n = in_sizes[0] / CC;      // 50000
    int e = in_sizes[2] / 2;       // 800000
    if (n > NN) n = NN;
    if (e > EE) e = EE;

    const int* dst = graph;
    const int* src = graph + e;

    // 0) init + bf16 hi/lo conversion
    init_kernel<<<(n + 255) / 256, 256>>>(rpe_w, rpe_b, n);
    conv_a_kernel<<<(n * CC + 255) / 256, 256>>>(feat, n);
    conv_b_kernel<<<(QKV_COLS * CC + 255) / 256, 256>>>(qkv_w);

    // 1) mma.sync bf16 3-term split QKV GEMM
    {
        static int attr_set = 0;
        if (!attr_set) {
            cudaFuncSetAttribute(mma_gemm_kernel,
                                 cudaFuncAttributeMaxDynamicSharedMemorySize, SM_TOT);
            attr_set = 1;
        }
        dim3 grid(QKV_COLS / TN, (n + TM - 1) / TM);
        mma_gemm_kernel<<<grid, 256, SM_TOT>>>(qkv_b, n);
    }

    // 2) CSR build by dst
    {
        int tb = 256;
        count_kernel<<<(e + tb - 1) / tb, tb>>>(dst, e);
        int nb = (n + SCAN_CHUNK - 1) / SCAN_CHUNK;
        scan1_kernel<<<nb, SCAN_CHUNK>>>(n);
        scan2_kernel<<<1, SCAN_CHUNK>>>(nb);
        scan3_kernel<<<nb, SCAN_CHUNK>>>(n, e);
        fill_kernel<<<(e + tb - 1) / tb, tb>>>(dst, src, e);
    }

    // 3) fused attention (1 warp / node)
    {
        int warps_per_block = 8;
        int tb = warps_per_block * 32;
        int grid = (n + warps_per_block - 1) / warps_per_block;
        attn_kernel<<<grid, tb>>>(coord, out, n);
    }
}

// round 8
// speedup vs baseline: 1.8693x; 1.0696x over previous
#include <cuda_runtime.h>
#include <cuda_bf16.h>
#include <math.h>
#include <stdint.h>

// Problem constants (shapes fixed by the dataset)
#define NN 50000
#define EE 800000
#define CC 128
#define HH 4
#define DD 32
#define QKV_COLS 384   // 3*C

#define SCAN_CHUNK 1024
#define NB_SCAN ((NN + SCAN_CHUNK - 1) / SCAN_CHUNK)   // 49

// GEMM: 3-term bf16 split D = ah*bh + al*bh + ah*bl, staged as 3 K=128 stages.
// smem per stage: A-half 32KB + B-half 32KB = 64KB -> 2 CTAs/SM.
#define TM 128
#define TN 128
#define SM_A 0
#define SM_B 32768
#define SM_TOT 65536

// ---------------- device scratch (no allocations allowed) ----------------
__device__ float g_qkv[NN * QKV_COLS];                        // 76.8 MB
__device__ __align__(16) __nv_bfloat16 g_a16[NN * 256];       // 25.6 MB  [m][hi(128)|lo(128)]
__device__ __align__(16) __nv_bfloat16 g_b16[QKV_COLS * 256]; // 0.2 MB   [n][hi|lo]
__device__ int   g_offsets[NN + 1];
__device__ int   g_cursor[NN];
__device__ int   g_esrc[EE];
__device__ int   g_bsum[NB_SCAN + 1];
__device__ __align__(16) float g_rpeh[HH * 4];

__device__ __forceinline__ uint32_t smem_to_u32(const void* p) {
    uint32_t a;
    asm("{ .reg .u64 t; cvta.to.shared.u64 t, %1; cvt.u32.u64 %0, t; }" : "=r"(a) : "l"(p));
    return a;
}
#define LDMATRIX_X4(r0, r1, r2, r3, addr) \
    asm volatile("ldmatrix.sync.aligned.m8n8.x4.shared.b16 {%0,%1,%2,%3}, [%4];" \
                 : "=r"(r0), "=r"(r1), "=r"(r2), "=r"(r3) : "r"(addr))
#define MMA_BF16(d, a, b0, b1) \
    asm volatile("mma.sync.aligned.m16n8k16.row.col.f32.bf16.bf16.f32 " \
                 "{%0,%1,%2,%3}, {%4,%5,%6,%7}, {%8,%9}, {%0,%1,%2,%3};" \
                 : "+f"((d)[0]), "+f"((d)[1]), "+f"((d)[2]), "+f"((d)[3]) \
                 : "r"((a)[0]), "r"((a)[1]), "r"((a)[2]), "r"((a)[3]), \
                   "r"(b0), "r"(b1))

// ---------------- 0) init: rpe collapse + zero degree counters ----------------
__global__ void init_kernel(const float* __restrict__ rpe_w,
                            const float* __restrict__ rpe_b, int n) {
    int i = blockIdx.x * blockDim.x + threadIdx.x;
    if (i < n) g_cursor[i] = 0;
    if (blockIdx.x == 0 && threadIdx.x < HH * 4) {
        int t = threadIdx.x;
        int h = t >> 2, p = t & 3;
        float s = 0.f;
        for (int d = 0; d < DD; d++) {
            int r = h * DD + d;
            s += (p < 3) ? rpe_w[r * 3 + p] : rpe_b[r];
        }
        g_rpeh[t] = s;
    }
}

// ---------------- 0b) fp32 -> bf16 hi/lo split ----------------
__global__ void conv_a_kernel(const float* __restrict__ feat, int n) {
    int idx = blockIdx.x * blockDim.x + threadIdx.x;
    if (idx >= n * CC) return;
    int m = idx >> 7, k = idx & 127;
    float x = feat[idx];
    __nv_bfloat16 h = __float2bfloat16(x);
    __nv_bfloat16 l = __float2bfloat16(x - __bfloat162float(h));
    g_a16[m * 256 + k] = h;
    g_a16[m * 256 + CC + k] = l;
}
__global__ void conv_b_kernel(const float* __restrict__ w) {
    int idx = blockIdx.x * blockDim.x + threadIdx.x;
    if (idx >= QKV_COLS * CC) return;
    int m = idx >> 7, k = idx & 127;
    float x = w[idx];
    __nv_bfloat16 h = __float2bfloat16(x);
    __nv_bfloat16 l = __float2bfloat16(x - __bfloat162float(h));
    g_b16[m * 256 + k] = h;
    g_b16[m * 256 + CC + k] = l;
}

// ---------------- 1) mma.sync bf16 3-term split GEMM (3-stage k loop) ----------------
// grid (3, ceil(M/128)), 256 threads = 8 warps, warp tile 64x32, 64KB smem.
// Stage s: A segment {hi, lo, hi}[s], B segment {hi, hi(skip reload), lo}[s].
__global__ __launch_bounds__(256, 2)
void mma_gemm_kernel(const float* __restrict__ bias, int M) {
    extern __shared__ char smem[];
    const uint32_t smA = smem_to_u32(smem) + SM_A;
    const uint32_t smB = smem_to_u32(smem) + SM_B;
    const int tid = threadIdx.x;
    const int lane = tid & 31;
    const int wid = tid >> 5;
    const int warpM = wid >> 2;   // 0..1  (64 rows each)
    const int warpN = wid & 3;    // 0..3  (32 cols each)
    const int m0 = blockIdx.y * TM;
    const int n0 = blockIdx.x * TN;

    float acc[4][4][4];
#pragma unroll
    for (int mt = 0; mt < 4; mt++)
#pragma unroll
        for (int nt = 0; nt < 4; nt++)
#pragma unroll
            for (int c = 0; c < 4; c++) acc[mt][nt][c] = 0.f;

    const int arow_base = warpM * 64 + (lane & 15);
    const int brow_base = warpN * 32 + (lane & 15);
    const int chalf = lane >> 4;    // 0 or 1: which 16B chunk of the k16 step

    const uint4* a4 = reinterpret_cast<const uint4*>(g_a16);
    const uint4* b4 = reinterpret_cast<const uint4*>(g_b16);
    const uint4 z4 = make_uint4(0u, 0u, 0u, 0u);

#pragma unroll
    for (int s = 0; s < 3; s++) {
        const int aseg = (s == 1) ? 1 : 0;   // hi, lo, hi
        const int bseg = (s == 2) ? 1 : 0;   // hi, hi, lo
        if (s) __syncthreads();              // WAR: previous compute done before overwrite

        // stage A-half: 128 rows x 256B (16 chunks of 16B per row), XOR-swizzled
#pragma unroll
        for (int i = 0; i < 8; i++) {
            int idx = tid + i * 256;          // 0..2047
            int row = idx >> 4;               // 0..127
            int c   = idx & 15;
            uint32_t off = (uint32_t)row * 256u + (uint32_t)((c ^ (row & 7)) << 4);
            int gm = m0 + row;
            uint4 av = (gm < M) ? a4[(size_t)gm * 32 + aseg * 16 + c] : z4;
            *reinterpret_cast<uint4*>(smem + SM_A + off) = av;
        }
        if (s != 1) {   // B unchanged between stage 0 and 1
#pragma unroll
            for (int i = 0; i < 8; i++) {
                int idx = tid + i * 256;
                int row = idx >> 4;
                int c   = idx & 15;
                uint32_t off = (uint32_t)row * 256u + (uint32_t)((c ^ (row & 7)) << 4);
                uint4 bv = b4[(size_t)(n0 + row) * 32 + bseg * 16 + c];
                *reinterpret_cast<uint4*>(smem + SM_B + off) = bv;
            }
        }
        __syncthreads();

        // 8 k16 steps over this K=128 half
#pragma unroll
        for (int ks = 0; ks < 8; ks++) {
            int c = ks * 2 + chalf;           // 0..15
            uint32_t af[4][4];
#pragma unroll
            for (int mt = 0; mt < 4; mt++) {
                int r = arow_base + mt * 16;
                uint32_t addr = smA + (uint32_t)r * 256u + (uint32_t)((c ^ (r & 7)) << 4);
                LDMATRIX_X4(af[mt][0], af[mt][1], af[mt][2], af[mt][3], addr);
            }
            uint32_t bf[2][4];
#pragma unroll
            for (int bt = 0; bt < 2; bt++) {
                int r = brow_base + bt * 16;
                uint32_t addr = smB + (uint32_t)r * 256u + (uint32_t)((c ^ (r & 7)) << 4);
                LDMATRIX_X4(bf[bt][0], bf[bt][1], bf[bt][2], bf[bt][3], addr);
            }
#pragma unroll
            for (int mt = 0; mt < 4; mt++)
#pragma unroll
                for (int nt = 0; nt < 4; nt++) {
                    int bt = nt >> 1, sub = nt & 1;
                    MMA_BF16(acc[mt][nt], af[mt], bf[bt][sub], bf[bt][sub + 2]);
                }
        }
    }

    // ---- epilogue: add bias, store float2 pairs ----
    const int groupID = lane >> 2;
    const int tq = lane & 3;
#pragma unroll
    for (int mt = 0; mt < 4; mt++) {
#pragma unroll
        for (int nt = 0; nt < 4; nt++) {
            int col = n0 + warpN * 32 + nt * 8 + tq * 2;
            float2 b = *reinterpret_cast<const float2*>(&bias[col]);
            int r0 = m0 + warpM * 64 + mt * 16 + groupID;
            if (r0 < M) {
                float2 o = make_float2(acc[mt][nt][0] + b.x, acc[mt][nt][1] + b.y);
                *reinterpret_cast<float2*>(&g_qkv[(size_t)r0 * QKV_COLS + col]) = o;
            }
            int r1 = r0 + 8;
            if (r1 < M) {
                float2 o = make_float2(acc[mt][nt][2] + b.x, acc[mt][nt][3] + b.y);
                *reinterpret_cast<float2*>(&g_qkv[(size_t)r1 * QKV_COLS + col]) = o;
            }
        }
    }
}

// ---------------- 2) CSR build ----------------
__global__ void count_kernel(const int* __restrict__ dst, int e) {
    int i = blockIdx.x * blockDim.x + threadIdx.x;
    if (i < e) atomicAdd(&g_cursor[dst[i]], 1);
}

__device__ __forceinline__ int block_scan_inclusive(int v, int* warp_sums) {
    int lane = threadIdx.x & 31;
    int wid  = threadIdx.x >> 5;
    int x = v;
#pragma unroll
    for (int off = 1; off < 32; off <<= 1) {
        int y = __shfl_up_sync(0xffffffffu, x, off);
        if (lane >= off) x += y;
    }
    if (lane == 31) warp_sums[wid] = x;
    __syncthreads();
    if (wid == 0) {
        int ws = warp_sums[lane];
#pragma unroll
        for (int off = 1; off < 32; off <<= 1) {
            int y = __shfl_up_sync(0xffffffffu, ws, off);
            if (lane >= off) ws += y;
        }
        warp_sums[lane] = ws;
    }
    __syncthreads();
    int base = (wid > 0) ? warp_sums[wid - 1] : 0;
    return base + x;
}

__global__ void scan1_kernel(int n) {
    __shared__ int warp_sums[32];
    int i = blockIdx.x * SCAN_CHUNK + threadIdx.x;
    int v = (i < n) ? g_cursor[i] : 0;
    int inc = block_scan_inclusive(v, warp_sums);
    if (i < n) g_offsets[i] = inc - v;
    if (threadIdx.x == SCAN_CHUNK - 1) g_bsum[blockIdx.x] = inc;
}
__global__ void scan2_kernel(int nb) {
    __shared__ int warp_sums[32];
    int v = (threadIdx.x < (unsigned)nb) ? g_bsum[threadIdx.x] : 0;
    int inc = block_scan_inclusive(v, warp_sums);
    if (threadIdx.x < (unsigned)nb) g_bsum[threadIdx.x] = inc - v;
}
__global__ void scan3_kernel(int n, int e) {
    int i = blockIdx.x * SCAN_CHUNK + threadIdx.x;
    if (i < n) {
        int off = g_offsets[i] + g_bsum[blockIdx.x];
        g_offsets[i] = off;
        g_cursor[i]  = off;
    }
    if (i == 0) g_offsets[n] = e;
}
__global__ void fill_kernel(const int* __restrict__ dst,
                            const int* __restrict__ src, int e) {
    int i = blockIdx.x * blockDim.x + threadIdx.x;
    if (i < e) {
        int d = dst[i];
        int pos = atomicAdd(&g_cursor[d], 1);
        g_esrc[pos] = src[i];
    }
}

// ---------------- 3) fused per-node online-softmax attention ----------------
__global__ void attn_kernel(const float* __restrict__ coord,
                            float* __restrict__ out, int n) {
    int warp_in_block = threadIdx.x >> 5;
    int node = blockIdx.x * (blockDim.x >> 5) + warp_in_block;
    if (node >= n) return;
    int lane = threadIdx.x & 31;
    int h = lane >> 3;

    float4 w = *reinterpret_cast<const float4*>(&g_rpeh[h * 4]);
    const float4 q4 = *reinterpret_cast<const float4*>(&g_qkv[node * QKV_COLS + lane * 4]);

    float cdx = coord[node * 3 + 0];
    float cdy = coord[node * 3 + 1];
    float cdz = coord[node * 3 + 2];

    int beg = g_offsets[node];
    int end = g_offsets[node + 1];

    float m = -INFINITY;
    float lsum = 0.f;
    float4 acc = make_float4(0.f, 0.f, 0.f, 0.f);

    int i = beg;
    for (; i + 1 < end; i += 2) {
        int s0 = g_esrc[i];
        int s1 = g_esrc[i + 1];
        const float4 k0 = *reinterpret_cast<const float4*>(&g_qkv[s0 * QKV_COLS + CC + lane * 4]);
        const float4 v0 = *reinterpret_cast<const float4*>(&g_qkv[s0 * QKV_COLS + 2 * CC + lane * 4]);
        const float4 k1 = *reinterpret_cast<const float4*>(&g_qkv[s1 * QKV_COLS + CC + lane * 4]);
        const float4 v1 = *reinterpret_cast<const float4*>(&g_qkv[s1 * QKV_COLS + 2 * CC + lane * 4]);

        float r0x = cdx - coord[s0 * 3 + 0];
        float r0y = cdy - coord[s0 * 3 + 1];
        float r0z = cdz - coord[s0 * 3 + 2];
        float r1x = cdx - coord[s1 * 3 + 0];
        float r1y = cdy - coord[s1 * 3 + 1];
        float r1z = cdz - coord[s1 * 3 + 2];

        float p0 = q4.x * k0.x + q4.y * k0.y + q4.z * k0.z + q4.w * k0.w;
        float p1 = q4.x * k1.x + q4.y * k1.y + q4.z * k1.z + q4.w * k1.w;
        p0 += __shfl_xor_sync(0xffffffffu, p0, 1);
        p1 += __shfl_xor_sync(0xffffffffu, p1, 1);
        p0 += __shfl_xor_sync(0xffffffffu, p0, 2);
        p1 += __shfl_xor_sync(0xffffffffu, p1, 2);
        p0 += __shfl_xor_sync(0xffffffffu, p0, 4);
        p1 += __shfl_xor_sync(0xffffffffu, p1, 4);

        float l0 = p0 + r0x * w.x + r0y * w.y + r0z * w.z + w.w;
        float l1 = p1 + r1x * w.x + r1y * w.y + r1z * w.z + w.w;

        float mn = fmaxf(m, fmaxf(l0, l1));
        float sc = __expf(m - mn);
        float e0 = __expf(l0 - mn);
        float e1 = __expf(l1 - mn);
        lsum = lsum * sc + e0 + e1;
        acc.x = acc.x * sc + e0 * v0.x + e1 * v1.x;
        acc.y = acc.y * sc + e0 * v0.y + e1 * v1.y;
        acc.z = acc.z * sc + e0 * v0.z + e1 * v1.z;
        acc.w = acc.w * sc + e0 * v0.w + e1 * v1.w;
        m = mn;
    }
    if (i < end) {
        int s0 = g_esrc[i];
        const float4 k0 = *reinterpret_cast<const float4*>(&g_qkv[s0 * QKV_COLS + CC + lane * 4]);
        const float4 v0 = *reinterpret_cast<const float4*>(&g_qkv[s0 * QKV_COLS + 2 * CC + lane * 4]);
        float rx = cdx - coord[s0 * 3 + 0];
        float ry = cdy - coord[s0 * 3 + 1];
        float rz = cdz - coord[s0 * 3 + 2];
        float p0 = q4.x * k0.x + q4.y * k0.y + q4.z * k0.z + q4.w * k0.w;
        p0 += __shfl_xor_sync(0xffffffffu, p0, 1);
        p0 += __shfl_xor_sync(0xffffffffu, p0, 2);
        p0 += __shfl_xor_sync(0xffffffffu, p0, 4);
        float l0 = p0 + rx * w.x + ry * w.y + rz * w.z + w.w;
        float mn = fmaxf(m, l0);
        float sc = __expf(m - mn);
        float e0 = __expf(l0 - mn);
        lsum = lsum * sc + e0;
        acc.x = acc.x * sc + e0 * v0.x;
        acc.y = acc.y * sc + e0 * v0.y;
        acc.z = acc.z * sc + e0 * v0.z;
        acc.w = acc.w * sc + e0 * v0.w;
        m = mn;
    }

    float inv = (lsum > 0.f) ? (1.f / lsum) : 0.f;
    float4 r = make_float4(acc.x * inv, acc.y * inv, acc.z * inv, acc.w * inv);
    *reinterpret_cast<float4*>(&out[node * CC + lane * 4]) = r;
}

// ---------------- launch ----------------
extern "C" void kernel_launch(void* const* d_in, const int* in_sizes, int n_in,
                              void* d_out, int out_size) {
    const float* feat   = (const float*)d_in[0];
    const float* coord  = (const float*)d_in[1];
    const int*   graph  = (const int*)d_in[2];
    const float* qkv_w  = (const float*)d_in[3];
    const float* qkv_b  = (const float*)d_in[4];
    const float* rpe_w  = (const float*)d_in[5];
    const float* rpe_b  = (const float*)d_in[6];
    float* out = (float*)d_out;

    int n = in_sizes[0] / CC;      // 50000
    int e = in_sizes[2] / 2;       // 800000
    if (n > NN) n = NN;
    if (e > EE) e = EE;

    const int* dst = graph;
    const int* src = graph + e;

    // 0) init + bf16 hi/lo conversion
    init_kernel<<<(n + 255) / 256, 256>>>(rpe_w, rpe_b, n);
    conv_a_kernel<<<(n * CC + 255) / 256, 256>>>(feat, n);
    conv_b_kernel<<<(QKV_COLS * CC + 255) / 256, 256>>>(qkv_w);

    // 1) mma.sync bf16 3-term split QKV GEMM (3-stage, 64KB smem, 2 CTAs/SM)
    {
        static int attr_set = 0;
        if (!attr_set) {
            cudaFuncSetAttribute(mma_gemm_kernel,
                                 cudaFuncAttributeMaxDynamicSharedMemorySize, SM_TOT);
            attr_set = 1;
        }
        dim3 grid(QKV_COLS / TN, (n + TM - 1) / TM);
        mma_gemm_kernel<<<grid, 256, SM_TOT>>>(qkv_b, n);
    }

    // 2) CSR build by dst
    {
        int tb = 256;
        count_kernel<<<(e + tb - 1) / tb, tb>>>(dst, e);
        int nb = (n + SCAN_CHUNK - 1) / SCAN_CHUNK;
        scan1_kernel<<<nb, SCAN_CHUNK>>>(n);
        scan2_kernel<<<1, SCAN_CHUNK>>>(nb);
        scan3_kernel<<<nb, SCAN_CHUNK>>>(n, e);
        fill_kernel<<<(e + tb - 1) / tb, tb>>>(dst, src, e);
    }

    // 3) fused attention (1 warp / node)
    {
        int warps_per_block = 8;
        int tb = warps_per_block * 32;
        int grid = (n + warps_per_block - 1) / warps_per_block;
        attn_kernel<<<grid, tb>>>(coord, out, n);
    }
}

// round 9
// speedup vs baseline: 1.9758x; 1.0570x over previous
#include <cuda_runtime.h>
#include <cuda_bf16.h>
#include <cuda_fp16.h>
#include <math.h>
#include <stdint.h>

// Problem constants (shapes fixed by the dataset)
#define NN 50000
#define EE 800000
#define CC 128
#define HH 4
#define DD 32
#define QKV_COLS 384   // 3*C

#define SCAN_CHUNK 1024
#define NB_SCAN ((NN + SCAN_CHUNK - 1) / SCAN_CHUNK)   // 49

// GEMM: 3-term bf16 split D = ah*bh + al*bh + ah*bl, staged as 3 K=128 stages.
#define TM 128
#define TN 128
#define SM_A 0
#define SM_B 32768
#define SM_TOT 65536

// ---------------- device scratch (no allocations allowed) ----------------
__device__ float g_qkv[NN * QKV_COLS];                        // 76.8 MB (v-part unused)
__device__ __align__(16) __half g_v16[NN * CC];               // 12.8 MB fp16 V
__device__ __align__(16) __nv_bfloat16 g_a16[NN * 256];       // 25.6 MB  [m][hi|lo]
__device__ __align__(16) __nv_bfloat16 g_b16[QKV_COLS * 256]; // 0.2 MB
__device__ int   g_offsets[NN + 1];
__device__ int   g_cursor[NN];
__device__ int   g_esrc[EE];
__device__ int   g_bsum[NB_SCAN + 1];
__device__ __align__(16) float g_rpeh[HH * 4];

__device__ __forceinline__ uint32_t smem_to_u32(const void* p) {
    uint32_t a;
    asm("{ .reg .u64 t; cvta.to.shared.u64 t, %1; cvt.u32.u64 %0, t; }" : "=r"(a) : "l"(p));
    return a;
}
#define LDMATRIX_X4(r0, r1, r2, r3, addr) \
    asm volatile("ldmatrix.sync.aligned.m8n8.x4.shared.b16 {%0,%1,%2,%3}, [%4];" \
                 : "=r"(r0), "=r"(r1), "=r"(r2), "=r"(r3) : "r"(addr))
#define MMA_BF16(d, a, b0, b1) \
    asm volatile("mma.sync.aligned.m16n8k16.row.col.f32.bf16.bf16.f32 " \
                 "{%0,%1,%2,%3}, {%4,%5,%6,%7}, {%8,%9}, {%0,%1,%2,%3};" \
                 : "+f"((d)[0]), "+f"((d)[1]), "+f"((d)[2]), "+f"((d)[3]) \
                 : "r"((a)[0]), "r"((a)[1]), "r"((a)[2]), "r"((a)[3]), \
                   "r"(b0), "r"(b1))

// ---------------- rpe collapse (main stream) ----------------
__global__ void rpe_kernel(const float* __restrict__ rpe_w,
                           const float* __restrict__ rpe_b) {
    int t = threadIdx.x;
    if (t >= HH * 4) return;
    int h = t >> 2, p = t & 3;
    float s = 0.f;
    for (int d = 0; d < DD; d++) {
        int r = h * DD + d;
        s += (p < 3) ? rpe_w[r * 3 + p] : rpe_b[r];
    }
    g_rpeh[t] = s;
}

// ---------------- zero degree counters (csr stream) ----------------
__global__ void zero_kernel(int n) {
    int i = blockIdx.x * blockDim.x + threadIdx.x;
    if (i < n) g_cursor[i] = 0;
}

// ---------------- fp32 -> bf16 hi/lo split ----------------
__global__ void conv_a_kernel(const float* __restrict__ feat, int n) {
    int idx = blockIdx.x * blockDim.x + threadIdx.x;
    if (idx >= n * CC) return;
    int m = idx >> 7, k = idx & 127;
    float x = feat[idx];
    __nv_bfloat16 h = __float2bfloat16(x);
    __nv_bfloat16 l = __float2bfloat16(x - __bfloat162float(h));
    g_a16[m * 256 + k] = h;
    g_a16[m * 256 + CC + k] = l;
}
__global__ void conv_b_kernel(const float* __restrict__ w) {
    int idx = blockIdx.x * blockDim.x + threadIdx.x;
    if (idx >= QKV_COLS * CC) return;
    int m = idx >> 7, k = idx & 127;
    float x = w[idx];
    __nv_bfloat16 h = __float2bfloat16(x);
    __nv_bfloat16 l = __float2bfloat16(x - __bfloat162float(h));
    g_b16[m * 256 + k] = h;
    g_b16[m * 256 + CC + k] = l;
}

// ---------------- mma.sync bf16 3-term split GEMM (3-stage k loop) ----------------
// grid (3, ceil(M/128)), 256 threads = 8 warps, warp tile 64x32, 64KB smem.
// blockIdx.x: 0 -> q cols, 1 -> k cols (fp32 out), 2 -> v cols (fp16 out).
__global__ __launch_bounds__(256, 2)
void mma_gemm_kernel(const float* __restrict__ bias, int M) {
    extern __shared__ char smem[];
    const uint32_t smA = smem_to_u32(smem) + SM_A;
    const uint32_t smB = smem_to_u32(smem) + SM_B;
    const int tid = threadIdx.x;
    const int lane = tid & 31;
    const int wid = tid >> 5;
    const int warpM = wid >> 2;
    const int warpN = wid & 3;
    const int m0 = blockIdx.y * TM;
    const int n0 = blockIdx.x * TN;

    float acc[4][4][4];
#pragma unroll
    for (int mt = 0; mt < 4; mt++)
#pragma unroll
        for (int nt = 0; nt < 4; nt++)
#pragma unroll
            for (int c = 0; c < 4; c++) acc[mt][nt][c] = 0.f;

    const int arow_base = warpM * 64 + (lane & 15);
    const int brow_base = warpN * 32 + (lane & 15);
    const int chalf = lane >> 4;

    const uint4* a4 = reinterpret_cast<const uint4*>(g_a16);
    const uint4* b4 = reinterpret_cast<const uint4*>(g_b16);
    const uint4 z4 = make_uint4(0u, 0u, 0u, 0u);

#pragma unroll
    for (int s = 0; s < 3; s++) {
        const int aseg = (s == 1) ? 1 : 0;   // hi, lo, hi
        const int bseg = (s == 2) ? 1 : 0;   // hi, hi, lo
        if (s) __syncthreads();

#pragma unroll
        for (int i = 0; i < 8; i++) {
            int idx = tid + i * 256;
            int row = idx >> 4;
            int c   = idx & 15;
            uint32_t off = (uint32_t)row * 256u + (uint32_t)((c ^ (row & 7)) << 4);
            int gm = m0 + row;
            uint4 av = (gm < M) ? a4[(size_t)gm * 32 + aseg * 16 + c] : z4;
            *reinterpret_cast<uint4*>(smem + SM_A + off) = av;
        }
        if (s != 1) {
#pragma unroll
            for (int i = 0; i < 8; i++) {
                int idx = tid + i * 256;
                int row = idx >> 4;
                int c   = idx & 15;
                uint32_t off = (uint32_t)row * 256u + (uint32_t)((c ^ (row & 7)) << 4);
                uint4 bv = b4[(size_t)(n0 + row) * 32 + bseg * 16 + c];
                *reinterpret_cast<uint4*>(smem + SM_B + off) = bv;
            }
        }
        __syncthreads();

#pragma unroll
        for (int ks = 0; ks < 8; ks++) {
            int c = ks * 2 + chalf;
            uint32_t af[4][4];
#pragma unroll
            for (int mt = 0; mt < 4; mt++) {
                int r = arow_base + mt * 16;
                uint32_t addr = smA + (uint32_t)r * 256u + (uint32_t)((c ^ (r & 7)) << 4);
                LDMATRIX_X4(af[mt][0], af[mt][1], af[mt][2], af[mt][3], addr);
            }
            uint32_t bf[2][4];
#pragma unroll
            for (int bt = 0; bt < 2; bt++) {
                int r = brow_base + bt * 16;
                uint32_t addr = smB + (uint32_t)r * 256u + (uint32_t)((c ^ (r & 7)) << 4);
                LDMATRIX_X4(bf[bt][0], bf[bt][1], bf[bt][2], bf[bt][3], addr);
            }
#pragma unroll
            for (int mt = 0; mt < 4; mt++)
#pragma unroll
                for (int nt = 0; nt < 4; nt++) {
                    int bt = nt >> 1, sub = nt & 1;
                    MMA_BF16(acc[mt][nt], af[mt], bf[bt][sub], bf[bt][sub + 2]);
                }
        }
    }

    // ---- epilogue: add bias; q/k blocks -> fp32 g_qkv, v block -> fp16 g_v16 ----
    const int groupID = lane >> 2;
    const int tq = lane & 3;
    const bool is_v = (blockIdx.x == 2);
#pragma unroll
    for (int mt = 0; mt < 4; mt++) {
#pragma unroll
        for (int nt = 0; nt < 4; nt++) {
            int colL = warpN * 32 + nt * 8 + tq * 2;      // 0..127 within tile
            int col = n0 + colL;
            float2 b = *reinterpret_cast<const float2*>(&bias[col]);
            int r0 = m0 + warpM * 64 + mt * 16 + groupID;
            int r1 = r0 + 8;
            float2 o0 = make_float2(acc[mt][nt][0] + b.x, acc[mt][nt][1] + b.y);
            float2 o1 = make_float2(acc[mt][nt][2] + b.x, acc[mt][nt][3] + b.y);
            if (is_v) {
                if (r0 < M)
                    *reinterpret_cast<__half2*>(&g_v16[(size_t)r0 * CC + colL]) =
                        __floats2half2_rn(o0.x, o0.y);
                if (r1 < M)
                    *reinterpret_cast<__half2*>(&g_v16[(size_t)r1 * CC + colL]) =
                        __floats2half2_rn(o1.x, o1.y);
            } else {
                if (r0 < M)
                    *reinterpret_cast<float2*>(&g_qkv[(size_t)r0 * QKV_COLS + col]) = o0;
                if (r1 < M)
                    *reinterpret_cast<float2*>(&g_qkv[(size_t)r1 * QKV_COLS + col]) = o1;
            }
        }
    }
}

// ---------------- CSR build ----------------
__global__ void count_kernel(const int* __restrict__ dst, int e) {
    int i = blockIdx.x * blockDim.x + threadIdx.x;
    if (i < e) atomicAdd(&g_cursor[dst[i]], 1);
}

__device__ __forceinline__ int block_scan_inclusive(int v, int* warp_sums) {
    int lane = threadIdx.x & 31;
    int wid  = threadIdx.x >> 5;
    int x = v;
#pragma unroll
    for (int off = 1; off < 32; off <<= 1) {
        int y = __shfl_up_sync(0xffffffffu, x, off);
        if (lane >= off) x += y;
    }
    if (lane == 31) warp_sums[wid] = x;
    __syncthreads();
    if (wid == 0) {
        int ws = warp_sums[lane];
#pragma unroll
        for (int off = 1; off < 32; off <<= 1) {
            int y = __shfl_up_sync(0xffffffffu, ws, off);
            if (lane >= off) ws += y;
        }
        warp_sums[lane] = ws;
    }
    __syncthreads();
    int base = (wid > 0) ? warp_sums[wid - 1] : 0;
    return base + x;
}

__global__ void scan1_kernel(int n) {
    __shared__ int warp_sums[32];
    int i = blockIdx.x * SCAN_CHUNK + threadIdx.x;
    int v = (i < n) ? g_cursor[i] : 0;
    int inc = block_scan_inclusive(v, warp_sums);
    if (i < n) g_offsets[i] = inc - v;
    if (threadIdx.x == SCAN_CHUNK - 1) g_bsum[blockIdx.x] = inc;
}
__global__ void scan2_kernel(int nb) {
    __shared__ int warp_sums[32];
    int v = (threadIdx.x < (unsigned)nb) ? g_bsum[threadIdx.x] : 0;
    int inc = block_scan_inclusive(v, warp_sums);
    if (threadIdx.x < (unsigned)nb) g_bsum[threadIdx.x] = inc - v;
}
__global__ void scan3_kernel(int n, int e) {
    int i = blockIdx.x * SCAN_CHUNK + threadIdx.x;
    if (i < n) {
        int off = g_offsets[i] + g_bsum[blockIdx.x];
        g_offsets[i] = off;
        g_cursor[i]  = off;
    }
    if (i == 0) g_offsets[n] = e;
}
__global__ void fill_kernel(const int* __restrict__ dst,
                            const int* __restrict__ src, int e) {
    int i = blockIdx.x * blockDim.x + threadIdx.x;
    if (i < e) {
        int d = dst[i];
        int pos = atomicAdd(&g_cursor[d], 1);
        g_esrc[pos] = src[i];
    }
}

// ---------------- fused per-node attention (no-max softmax, fp16 V) ----------------
__global__ void attn_kernel(const float* __restrict__ coord,
                            float* __restrict__ out, int n) {
    int warp_in_block = threadIdx.x >> 5;
    int node = blockIdx.x * (blockDim.x >> 5) + warp_in_block;
    if (node >= n) return;
    int lane = threadIdx.x & 31;
    int h = lane >> 3;

    float4 w = *reinterpret_cast<const float4*>(&g_rpeh[h * 4]);
    const float4 q4 = *reinterpret_cast<const float4*>(&g_qkv[node * QKV_COLS + lane * 4]);

    float cdx = coord[node * 3 + 0];
    float cdy = coord[node * 3 + 1];
    float cdz = coord[node * 3 + 2];

    int beg = g_offsets[node];
    int end = g_offsets[node + 1];

    float lsum = 0.f;
    float4 acc = make_float4(0.f, 0.f, 0.f, 0.f);

    int i = beg;
    for (; i + 1 < end; i += 2) {
        int s0 = g_esrc[i];
        int s1 = g_esrc[i + 1];
        const float4 k0 = *reinterpret_cast<const float4*>(&g_qkv[s0 * QKV_COLS + CC + lane * 4]);
        const float4 k1 = *reinterpret_cast<const float4*>(&g_qkv[s1 * QKV_COLS + CC + lane * 4]);
        const uint2 vr0 = *reinterpret_cast<const uint2*>(&g_v16[(size_t)s0 * CC + lane * 4]);
        const uint2 vr1 = *reinterpret_cast<const uint2*>(&g_v16[(size_t)s1 * CC + lane * 4]);

        float r0x = cdx - coord[s0 * 3 + 0];
        float r0y = cdy - coord[s0 * 3 + 1];
        float r0z = cdz - coord[s0 * 3 + 2];
        float r1x = cdx - coord[s1 * 3 + 0];
        float r1y = cdy - coord[s1 * 3 + 1];
        float r1z = cdz - coord[s1 * 3 + 2];

        float p0 = q4.x * k0.x + q4.y * k0.y + q4.z * k0.z + q4.w * k0.w;
        float p1 = q4.x * k1.x + q4.y * k1.y + q4.z * k1.z + q4.w * k1.w;
        p0 += __shfl_xor_sync(0xffffffffu, p0, 1);
        p1 += __shfl_xor_sync(0xffffffffu, p1, 1);
        p0 += __shfl_xor_sync(0xffffffffu, p0, 2);
        p1 += __shfl_xor_sync(0xffffffffu, p1, 2);
        p0 += __shfl_xor_sync(0xffffffffu, p0, 4);
        p1 += __shfl_xor_sync(0xffffffffu, p1, 4);

        float l0 = p0 + r0x * w.x + r0y * w.y + r0z * w.z + w.w;
        float l1 = p1 + r1x * w.x + r1y * w.y + r1z * w.z + w.w;
        float e0 = __expf(l0);
        float e1 = __expf(l1);
        lsum += e0 + e1;

        float2 v0a = __half22float2(*reinterpret_cast<const __half2*>(&vr0.x));
        float2 v0b = __half22float2(*reinterpret_cast<const __half2*>(&vr0.y));
        float2 v1a = __half22float2(*reinterpret_cast<const __half2*>(&vr1.x));
        float2 v1b = __half22float2(*reinterpret_cast<const __half2*>(&vr1.y));
        acc.x += e0 * v0a.x + e1 * v1a.x;
        acc.y += e0 * v0a.y + e1 * v1a.y;
        acc.z += e0 * v0b.x + e1 * v1b.x;
        acc.w += e0 * v0b.y + e1 * v1b.y;
    }
    if (i < end) {
        int s0 = g_esrc[i];
        const float4 k0 = *reinterpret_cast<const float4*>(&g_qkv[s0 * QKV_COLS + CC + lane * 4]);
        const uint2 vr0 = *reinterpret_cast<const uint2*>(&g_v16[(size_t)s0 * CC + lane * 4]);
        float rx = cdx - coord[s0 * 3 + 0];
        float ry = cdy - coord[s0 * 3 + 1];
        float rz = cdz - coord[s0 * 3 + 2];
        float p0 = q4.x * k0.x + q4.y * k0.y + q4.z * k0.z + q4.w * k0.w;
        p0 += __shfl_xor_sync(0xffffffffu, p0, 1);
        p0 += __shfl_xor_sync(0xffffffffu, p0, 2);
        p0 += __shfl_xor_sync(0xffffffffu, p0, 4);
        float l0 = p0 + rx * w.x + ry * w.y + rz * w.z + w.w;
        float e0 = __expf(l0);
        lsum += e0;
        float2 v0a = __half22float2(*reinterpret_cast<const __half2*>(&vr0.x));
        float2 v0b = __half22float2(*reinterpret_cast<const __half2*>(&vr0.y));
        acc.x += e0 * v0a.x;
        acc.y += e0 * v0a.y;
        acc.z += e0 * v0b.x;
        acc.w += e0 * v0b.y;
    }

    float inv = (lsum > 0.f) ? (1.f / lsum) : 0.f;
    float4 r = make_float4(acc.x * inv, acc.y * inv, acc.z * inv, acc.w * inv);
    *reinterpret_cast<float4*>(&out[node * CC + lane * 4]) = r;
}

// ---------------- launch ----------------
extern "C" void kernel_launch(void* const* d_in, const int* in_sizes, int n_in,
                              void* d_out, int out_size) {
    const float* feat   = (const float*)d_in[0];
    const float* coord  = (const float*)d_in[1];
    const int*   graph  = (const int*)d_in[2];
    const float* qkv_w  = (const float*)d_in[3];
    const float* qkv_b  = (const float*)d_in[4];
    const float* rpe_w  = (const float*)d_in[5];
    const float* rpe_b  = (const float*)d_in[6];
    float* out = (float*)d_out;

    int n = in_sizes[0] / CC;      // 50000
    int e = in_sizes[2] / 2;       // 800000
    if (n > NN) n = NN;
    if (e > EE) e = EE;

    const int* dst = graph;
    const int* src = graph + e;

    static cudaStream_t s2 = nullptr;
    static cudaEvent_t evFork = nullptr, evJoin = nullptr;
    if (!s2) {
        cudaStreamCreateWithFlags(&s2, cudaStreamNonBlocking);
        cudaEventCreateWithFlags(&evFork, cudaEventDisableTiming);
        cudaEventCreateWithFlags(&evJoin, cudaEventDisableTiming);
        cudaFuncSetAttribute(mma_gemm_kernel,
                             cudaFuncAttributeMaxDynamicSharedMemorySize, SM_TOT);
    }

    // fork: CSR build chain on s2, GEMM chain on main
    cudaEventRecord(evFork, 0);
    cudaStreamWaitEvent(s2, evFork, 0);

    {   // ---- s2: CSR build by dst ----
        int tb = 256;
        zero_kernel<<<(n + tb - 1) / tb, tb, 0, s2>>>(n);
        count_kernel<<<(e + tb - 1) / tb, tb, 0, s2>>>(dst, e);
        int nb = (n + SCAN_CHUNK - 1) / SCAN_CHUNK;
        scan1_kernel<<<nb, SCAN_CHUNK, 0, s2>>>(n);
        scan2_kernel<<<1, SCAN_CHUNK, 0, s2>>>(nb);
        scan3_kernel<<<nb, SCAN_CHUNK, 0, s2>>>(n, e);
        fill_kernel<<<(e + tb - 1) / tb, tb, 0, s2>>>(dst, src, e);
        cudaEventRecord(evJoin, s2);
    }

    {   // ---- main: rpe + conv + GEMM ----
        rpe_kernel<<<1, 32>>>(rpe_w, rpe_b);
        conv_a_kernel<<<(n * CC + 255) / 256, 256>>>(feat, n);
        conv_b_kernel<<<(QKV_COLS * CC + 255) / 256, 256>>>(qkv_w);
        dim3 grid(QKV_COLS / TN, (n + TM - 1) / TM);
        mma_gemm_kernel<<<grid, 256, SM_TOT>>>(qkv_b, n);
    }

    // join, then attention
    cudaStreamWaitEvent(0, evJoin, 0);
    {
        int warps_per_block = 8;
        int tb = warps_per_block * 32;
        int grid = (n + warps_per_block - 1) / warps_per_block;
        attn_kernel<<<grid, tb>>>(coord, out, n);
    }
}

// round 11
// speedup vs baseline: 2.1474x; 1.0868x over previous
#include <cuda_runtime.h>
#include <cuda_bf16.h>
#include <cuda_fp16.h>
#include <math.h>
#include <stdint.h>

// Problem constants (shapes fixed by the dataset)
#define NN 50000
#define EE 800000
#define CC 128
#define HH 4
#define DD 32
#define QKV_COLS 384   // 3*C

#define SCAN_CHUNK 1024
#define NB_SCAN ((NN + SCAN_CHUNK - 1) / SCAN_CHUNK)   // 49

// GEMM: 3-term bf16 split D = ah*bh + al*bh + ah*bl as 12 pipelined K=32 chunks.
#define TM 128
#define TN 128
#define NCHUNK 12
#define CHUNK_A_BYTES 8192          // 128 rows x 64B
#define BUF_BYTES 16384             // A chunk + B chunk
#define SM_TOT (3 * BUF_BYTES)      // 49152, 3-deep ring -> 2 CTAs/SM

// ---------------- device scratch (no allocations allowed) ----------------
__device__ float g_qkv[NN * QKV_COLS];                        // q,k fp32 (v slots unused)
__device__ __align__(16) __half g_v16[NN * CC];               // fp16 V
__device__ __align__(16) __nv_bfloat16 g_a16[NN * 256];       // [m][hi(128)|lo(128)]
__device__ __align__(16) __nv_bfloat16 g_b16[QKV_COLS * 256];
__device__ int   g_offsets[NN + 1];
__device__ int   g_cursor[NN];
__device__ int   g_esrc[EE];
__device__ int   g_bsum[NB_SCAN + 1];
__device__ __align__(16) float g_rpeh[HH * 4];

__device__ __forceinline__ uint32_t smem_to_u32(const void* p) {
    uint32_t a;
    asm("{ .reg .u64 t; cvta.to.shared.u64 t, %1; cvt.u32.u64 %0, t; }" : "=r"(a) : "l"(p));
    return a;
}
#define LDMATRIX_X4(r0, r1, r2, r3, addr) \
    asm volatile("ldmatrix.sync.aligned.m8n8.x4.shared.b16 {%0,%1,%2,%3}, [%4];" \
                 : "=r"(r0), "=r"(r1), "=r"(r2), "=r"(r3) : "r"(addr))
#define MMA_BF16(d, a, b0, b1) \
    asm volatile("mma.sync.aligned.m16n8k16.row.col.f32.bf16.bf16.f32 " \
                 "{%0,%1,%2,%3}, {%4,%5,%6,%7}, {%8,%9}, {%0,%1,%2,%3};" \
                 : "+f"((d)[0]), "+f"((d)[1]), "+f"((d)[2]), "+f"((d)[3]) \
                 : "r"((a)[0]), "r"((a)[1]), "r"((a)[2]), "r"((a)[3]), \
                   "r"(b0), "r"(b1))
#define CP_ASYNC16(smem_addr, gptr, szbytes) \
    asm volatile("cp.async.cg.shared.global [%0], [%1], 16, %2;" \
                 :: "r"(smem_addr), "l"(gptr), "r"(szbytes) : "memory")
#define CP_COMMIT() asm volatile("cp.async.commit_group;" ::: "memory")

// chunk layout: 128 rows x 32 bf16 (64B). Two rows share a 128B line; swizzle
// keeps both cp.async stores and ldmatrix reads bank-conflict-free.
__device__ __forceinline__ uint32_t chunk_off(int r, int c) {
    return (uint32_t)((r >> 1) * 128 + (r & 1) * 64 + (((c ^ ((r >> 1) & 3)) & 3) << 4));
}

// ---------------- rpe collapse (main stream) ----------------
__global__ void rpe_kernel(const float* __restrict__ rpe_w,
                           const float* __restrict__ rpe_b) {
    int t = threadIdx.x;
    if (t >= HH * 4) return;
    int h = t >> 2, p = t & 3;
    float s = 0.f;
    for (int d = 0; d < DD; d++) {
        int r = h * DD + d;
        s += (p < 3) ? rpe_w[r * 3 + p] : rpe_b[r];
    }
    g_rpeh[t] = s;
}

// ---------------- zero degree counters (csr stream) ----------------
__global__ void zero_kernel(int n) {
    int i = blockIdx.x * blockDim.x + threadIdx.x;
    if (i < n) g_cursor[i] = 0;
}

// ---------------- fp32 -> bf16 hi/lo split ----------------
__global__ void conv_a_kernel(const float* __restrict__ feat, int n) {
    int idx = blockIdx.x * blockDim.x + threadIdx.x;
    if (idx >= n * CC) return;
    int m = idx >> 7, k = idx & 127;
    float x = feat[idx];
    __nv_bfloat16 h = __float2bfloat16(x);
    __nv_bfloat16 l = __float2bfloat16(x - __bfloat162float(h));
    g_a16[m * 256 + k] = h;
    g_a16[m * 256 + CC + k] = l;
}
__global__ void conv_b_kernel(const float* __restrict__ w) {
    int idx = blockIdx.x * blockDim.x + threadIdx.x;
    if (idx >= QKV_COLS * CC) return;
    int m = idx >> 7, k = idx & 127;
    float x = w[idx];
    __nv_bfloat16 h = __float2bfloat16(x);
    __nv_bfloat16 l = __float2bfloat16(x - __bfloat162float(h));
    g_b16[m * 256 + k] = h;
    g_b16[m * 256 + CC + k] = l;
}

// ---------------- cp.async-pipelined bf16 3-term split GEMM ----------------
// grid (3, ceil(M/128)), 256 threads = 8 warps, warp tile 64x32, 48KB smem ring.
__global__ __launch_bounds__(256, 2)
void mma_gemm_kernel(const float* __restrict__ bias, int M) {
    extern __shared__ char smem[];
    const uint32_t smbase = smem_to_u32(smem);
    const int tid = threadIdx.x;
    const int lane = tid & 31;
    const int wid = tid >> 5;
    const int warpM = wid >> 2;
    const int warpN = wid & 3;
    const int m0 = blockIdx.y * TM;
    const int n0 = blockIdx.x * TN;

    // virtual K=384 chunk maps (k32 granularity; 8 chunks per operand row)
    const int aidx[NCHUNK] = {0, 1, 2, 3, 4, 5, 6, 7, 0, 1, 2, 3}; // ah, al, ah
    const int bidx[NCHUNK] = {0, 1, 2, 3, 0, 1, 2, 3, 4, 5, 6, 7}; // bh, bh, bl

    const uint4* a4 = reinterpret_cast<const uint4*>(g_a16);
    const uint4* b4 = reinterpret_cast<const uint4*>(g_b16);

    // thread's fixed staging slot: 2 x 16B for A, 2 x 16B for B per chunk
    const int sr0 = tid >> 2, sc0 = tid & 3;          // idx 0..255
    const int sr1 = (tid + 256) >> 2, sc1 = (tid + 256) & 3;
    const uint32_t soA0 = chunk_off(sr0, sc0), soA1 = chunk_off(sr1, sc1);

    auto ld_chunk = [&](int buf, int ac, int bc) {
        uint32_t base = smbase + (uint32_t)buf * BUF_BYTES;
        int szA0 = (m0 + sr0 < M) ? 16 : 0;
        int szA1 = (m0 + sr1 < M) ? 16 : 0;
        CP_ASYNC16(base + soA0, a4 + (size_t)(m0 + sr0) * 32 + ac * 4 + sc0, szA0);
        CP_ASYNC16(base + soA1, a4 + (size_t)(m0 + sr1) * 32 + ac * 4 + sc1, szA1);
        uint32_t baseB = base + CHUNK_A_BYTES;
        CP_ASYNC16(baseB + soA0, b4 + (size_t)(n0 + sr0) * 32 + bc * 4 + sc0, 16);
        CP_ASYNC16(baseB + soA1, b4 + (size_t)(n0 + sr1) * 32 + bc * 4 + sc1, 16);
        CP_COMMIT();
    };

    float acc[4][4][4];
#pragma unroll
    for (int mt = 0; mt < 4; mt++)
#pragma unroll
        for (int nt = 0; nt < 4; nt++)
#pragma unroll
            for (int c = 0; c < 4; c++) acc[mt][nt][c] = 0.f;

    const int arow_base = warpM * 64 + (lane & 15);
    const int brow_base = warpN * 32 + (lane & 15);
    const int chalf = lane >> 4;

    ld_chunk(0, aidx[0], bidx[0]);
    ld_chunk(1, aidx[1], bidx[1]);

#pragma unroll
    for (int t = 0; t < NCHUNK; t++) {
        if (t < NCHUNK - 1) asm volatile("cp.async.wait_group 1;" ::: "memory");
        else               asm volatile("cp.async.wait_group 0;" ::: "memory");
        __syncthreads();
        if (t + 2 < NCHUNK) ld_chunk((t + 2) % 3, aidx[t + 2], bidx[t + 2]);

        uint32_t bufA = smbase + (uint32_t)(t % 3) * BUF_BYTES;
        uint32_t bufB = bufA + CHUNK_A_BYTES;
#pragma unroll
        for (int ks2 = 0; ks2 < 2; ks2++) {
            int c = ks2 * 2 + chalf;
            uint32_t af[4][4];
#pragma unroll
            for (int mt = 0; mt < 4; mt++) {
                int r = arow_base + mt * 16;
                LDMATRIX_X4(af[mt][0], af[mt][1], af[mt][2], af[mt][3],
                            bufA + chunk_off(r, c));
            }
            uint32_t bf[2][4];
#pragma unroll
            for (int bt = 0; bt < 2; bt++) {
                int r = brow_base + bt * 16;
                LDMATRIX_X4(bf[bt][0], bf[bt][1], bf[bt][2], bf[bt][3],
                            bufB + chunk_off(r, c));
            }
#pragma unroll
            for (int mt = 0; mt < 4; mt++)
#pragma unroll
                for (int nt = 0; nt < 4; nt++) {
                    int bt = nt >> 1, sub = nt & 1;
                    MMA_BF16(acc[mt][nt], af[mt], bf[bt][sub], bf[bt][sub + 2]);
                }
        }
    }

    // ---- epilogue: add bias; q/k -> fp32 g_qkv, v -> fp16 g_v16 ----
    const int groupID = lane >> 2;
    const int tq = lane & 3;
    const bool is_v = (blockIdx.x == 2);
#pragma unroll
    for (int mt = 0; mt < 4; mt++) {
#pragma unroll
        for (int nt = 0; nt < 4; nt++) {
            int colL = warpN * 32 + nt * 8 + tq * 2;
            int col = n0 + colL;
            float2 b = *reinterpret_cast<const float2*>(&bias[col]);
            int r0 = m0 + warpM * 64 + mt * 16 + groupID;
            int r1 = r0 + 8;
            float2 o0 = make_float2(acc[mt][nt][0] + b.x, acc[mt][nt][1] + b.y);
            float2 o1 = make_float2(acc[mt][nt][2] + b.x, acc[mt][nt][3] + b.y);
            if (is_v) {
                if (r0 < M)
                    *reinterpret_cast<__half2*>(&g_v16[(size_t)r0 * CC + colL]) =
                        __floats2half2_rn(o0.x, o0.y);
                if (r1 < M)
                    *reinterpret_cast<__half2*>(&g_v16[(size_t)r1 * CC + colL]) =
                        __floats2half2_rn(o1.x, o1.y);
            } else {
                if (r0 < M)
                    *reinterpret_cast<float2*>(&g_qkv[(size_t)r0 * QKV_COLS + col]) = o0;
                if (r1 < M)
                    *reinterpret_cast<float2*>(&g_qkv[(size_t)r1 * QKV_COLS + col]) = o1;
            }
        }
    }
}

// ---------------- CSR build ----------------
__global__ void count_kernel(const int* __restrict__ dst, int e) {
    int i = blockIdx.x * blockDim.x + threadIdx.x;
    if (i < e) atomicAdd(&g_cursor[dst[i]], 1);
}

__device__ __forceinline__ int block_scan_inclusive(int v, int* warp_sums) {
    int lane = threadIdx.x & 31;
    int wid  = threadIdx.x >> 5;
    int x = v;
#pragma unroll
    for (int off = 1; off < 32; off <<= 1) {
        int y = __shfl_up_sync(0xffffffffu, x, off);
        if (lane >= off) x += y;
    }
    if (lane == 31) warp_sums[wid] = x;
    __syncthreads();
    if (wid == 0) {
        int ws = warp_sums[lane];
#pragma unroll
        for (int off = 1; off < 32; off <<= 1) {
            int y = __shfl_up_sync(0xffffffffu, ws, off);
            if (lane >= off) ws += y;
        }
        warp_sums[lane] = ws;
    }
    __syncthreads();
    int base = (wid > 0) ? warp_sums[wid - 1] : 0;
    return base + x;
}

__global__ void scan1_kernel(int n) {
    __shared__ int warp_sums[32];
    int i = blockIdx.x * SCAN_CHUNK + threadIdx.x;
    int v = (i < n) ? g_cursor[i] : 0;
    int inc = block_scan_inclusive(v, warp_sums);
    if (i < n) g_offsets[i] = inc - v;
    if (threadIdx.x == SCAN_CHUNK - 1) g_bsum[blockIdx.x] = inc;
}
__global__ void scan2_kernel(int nb) {
    __shared__ int warp_sums[32];
    int v = (threadIdx.x < (unsigned)nb) ? g_bsum[threadIdx.x] : 0;
    int inc = block_scan_inclusive(v, warp_sums);
    if (threadIdx.x < (unsigned)nb) g_bsum[threadIdx.x] = inc - v;
}
__global__ void scan3_kernel(int n, int e) {
    int i = blockIdx.x * SCAN_CHUNK + threadIdx.x;
    if (i < n) {
        int off = g_offsets[i] + g_bsum[blockIdx.x];
        g_offsets[i] = off;
        g_cursor[i]  = off;
    }
    if (i == 0) g_offsets[n] = e;
}
__global__ void fill_kernel(const int* __restrict__ dst,
                            const int* __restrict__ src, int e) {
    int i = blockIdx.x * blockDim.x + threadIdx.x;
    if (i < e) {
        int d = dst[i];
        int pos = atomicAdd(&g_cursor[d], 1);
        g_esrc[pos] = src[i];
    }
}

// ---------------- fused per-node attention (no-max softmax, fp16 V) ----------------
__global__ void attn_kernel(const float* __restrict__ coord,
                            float* __restrict__ out, int n) {
    int warp_in_block = threadIdx.x >> 5;
    int node = blockIdx.x * (blockDim.x >> 5) + warp_in_block;
    if (node >= n) return;
    int lane = threadIdx.x & 31;
    int h = lane >> 3;

    float4 w = *reinterpret_cast<const float4*>(&g_rpeh[h * 4]);
    const float4 q4 = *reinterpret_cast<const float4*>(&g_qkv[node * QKV_COLS + lane * 4]);

    float cdx = coord[node * 3 + 0];
    float cdy = coord[node * 3 + 1];
    float cdz = coord[node * 3 + 2];

    int beg = g_offsets[node];
    int end = g_offsets[node + 1];

    float lsum = 0.f;
    float4 acc = make_float4(0.f, 0.f, 0.f, 0.f);

    int i = beg;
    for (; i + 1 < end; i += 2) {
        int s0 = g_esrc[i];
        int s1 = g_esrc[i + 1];
        const float4 k0 = *reinterpret_cast<const float4*>(&g_qkv[s0 * QKV_COLS + CC + lane * 4]);
        const float4 k1 = *reinterpret_cast<const float4*>(&g_qkv[s1 * QKV_COLS + CC + lane * 4]);
        const uint2 vr0 = *reinterpret_cast<const uint2*>(&g_v16[(size_t)s0 * CC + lane * 4]);
        const uint2 vr1 = *reinterpret_cast<const uint2*>(&g_v16[(size_t)s1 * CC + lane * 4]);

        float r0x = cdx - coord[s0 * 3 + 0];
        float r0y = cdy - coord[s0 * 3 + 1];
        float r0z = cdz - coord[s0 * 3 + 2];
        float r1x = cdx - coord[s1 * 3 + 0];
        float r1y = cdy - coord[s1 * 3 + 1];
        float r1z = cdz - coord[s1 * 3 + 2];

        float p0 = q4.x * k0.x + q4.y * k0.y + q4.z * k0.z + q4.w * k0.w;
        float p1 = q4.x * k1.x + q4.y * k1.y + q4.z * k1.z + q4.w * k1.w;
        p0 += __shfl_xor_sync(0xffffffffu, p0, 1);
        p1 += __shfl_xor_sync(0xffffffffu, p1, 1);
        p0 += __shfl_xor_sync(0xffffffffu, p0, 2);
        p1 += __shfl_xor_sync(0xffffffffu, p1, 2);
        p0 += __shfl_xor_sync(0xffffffffu, p0, 4);
        p1 += __shfl_xor_sync(0xffffffffu, p1, 4);

        float l0 = p0 + r0x * w.x + r0y * w.y + r0z * w.z + w.w;
        float l1 = p1 + r1x * w.x + r1y * w.y + r1z * w.z + w.w;
        float e0 = __expf(l0);
        float e1 = __expf(l1);
        lsum += e0 + e1;

        float2 v0a = __half22float2(*reinterpret_cast<const __half2*>(&vr0.x));
        float2 v0b = __half22float2(*reinterpret_cast<const __half2*>(&vr0.y));
        float2 v1a = __half22float2(*reinterpret_cast<const __half2*>(&vr1.x));
        float2 v1b = __half22float2(*reinterpret_cast<const __half2*>(&vr1.y));
        acc.x += e0 * v0a.x + e1 * v1a.x;
        acc.y += e0 * v0a.y + e1 * v1a.y;
        acc.z += e0 * v0b.x + e1 * v1b.x;
        acc.w += e0 * v0b.y + e1 * v1b.y;
    }
    if (i < end) {
        int s0 = g_esrc[i];
        const float4 k0 = *reinterpret_cast<const float4*>(&g_qkv[s0 * QKV_COLS + CC + lane * 4]);
        const uint2 vr0 = *reinterpret_cast<const uint2*>(&g_v16[(size_t)s0 * CC + lane * 4]);
        float rx = cdx - coord[s0 * 3 + 0];
        float ry = cdy - coord[s0 * 3 + 1];
        float rz = cdz - coord[s0 * 3 + 2];
        float p0 = q4.x * k0.x + q4.y * k0.y + q4.z * k0.z + q4.w * k0.w;
        p0 += __shfl_xor_sync(0xffffffffu, p0, 1);
        p0 += __shfl_xor_sync(0xffffffffu, p0, 2);
        p0 += __shfl_xor_sync(0xffffffffu, p0, 4);
        float l0 = p0 + rx * w.x + ry * w.y + rz * w.z + w.w;
        float e0 = __expf(l0);
        lsum += e0;
        float2 v0a = __half22float2(*reinterpret_cast<const __half2*>(&vr0.x));
        float2 v0b = __half22float2(*reinterpret_cast<const __half2*>(&vr0.y));
        acc.x += e0 * v0a.x;
        acc.y += e0 * v0a.y;
        acc.z += e0 * v0b.x;
        acc.w += e0 * v0b.y;
    }

    float inv = (lsum > 0.f) ? (1.f / lsum) : 0.f;
    float4 r = make_float4(acc.x * inv, acc.y * inv, acc.z * inv, acc.w * inv);
    *reinterpret_cast<float4*>(&out[node * CC + lane * 4]) = r;
}

// ---------------- launch ----------------
extern "C" void kernel_launch(void* const* d_in, const int* in_sizes, int n_in,
                              void* d_out, int out_size) {
    const float* feat   = (const float*)d_in[0];
    const float* coord  = (const float*)d_in[1];
    const int*   graph  = (const int*)d_in[2];
    const float* qkv_w  = (const float*)d_in[3];
    const float* qkv_b  = (const float*)d_in[4];
    const float* rpe_w  = (const float*)d_in[5];
    const float* rpe_b  = (const float*)d_in[6];
    float* out = (float*)d_out;

    int n = in_sizes[0] / CC;      // 50000
    int e = in_sizes[2] / 2;       // 800000
    if (n > NN) n = NN;
    if (e > EE) e = EE;

    const int* dst = graph;
    const int* src = graph + e;

    static cudaStream_t s2 = nullptr;
    static cudaEvent_t evFork = nullptr, evJoin = nullptr;
    if (!s2) {
        cudaStreamCreateWithFlags(&s2, cudaStreamNonBlocking);
        cudaEventCreateWithFlags(&evFork, cudaEventDisableTiming);
        cudaEventCreateWithFlags(&evJoin, cudaEventDisableTiming);
        cudaFuncSetAttribute(mma_gemm_kernel,
                             cudaFuncAttributeMaxDynamicSharedMemorySize, SM_TOT);
    }

    // fork: CSR build chain on s2, GEMM chain on main
    cudaEventRecord(evFork, 0);
    cudaStreamWaitEvent(s2, evFork, 0);

    {   // ---- s2: CSR build by dst ----
        int tb = 256;
        zero_kernel<<<(n + tb - 1) / tb, tb, 0, s2>>>(n);
        count_kernel<<<(e + tb - 1) / tb, tb, 0, s2>>>(dst, e);
        int nb = (n + SCAN_CHUNK - 1) / SCAN_CHUNK;
        scan1_kernel<<<nb, SCAN_CHUNK, 0, s2>>>(n);
        scan2_kernel<<<1, SCAN_CHUNK, 0, s2>>>(nb);
        scan3_kernel<<<nb, SCAN_CHUNK, 0, s2>>>(n, e);
        fill_kernel<<<(e + tb - 1) / tb, tb, 0, s2>>>(dst, src, e);
        cudaEventRecord(evJoin, s2);
    }

    {   // ---- main: rpe + conv + GEMM ----
        rpe_kernel<<<1, 32>>>(rpe_w, rpe_b);
        conv_a_kernel<<<(n * CC + 255) / 256, 256>>>(feat, n);
        conv_b_kernel<<<(QKV_COLS * CC + 255) / 256, 256>>>(qkv_w);
        dim3 grid(QKV_COLS / TN, (n + TM - 1) / TM);
        mma_gemm_kernel<<<grid, 256, SM_TOT>>>(qkv_b, n);
    }

    // join, then attention
    cudaStreamWaitEvent(0, evJoin, 0);
    {
        int warps_per_block = 8;
        int tb = warps_per_block * 32;
        int grid = (n + warps_per_block - 1) / warps_per_block;
        attn_kernel<<<grid, tb>>>(coord, out, n);
    }
}

// round 14
// speedup vs baseline: 2.3029x; 1.0725x over previous
#include <cuda_runtime.h>
#include <cuda_bf16.h>
#include <cuda_fp16.h>
#include <math.h>
#include <stdint.h>

// Problem constants (shapes fixed by the dataset)
#define NN 50000
#define EE 800000
#define CC 128
#define HH 4
#define DD 32
#define QKV_COLS 384   // 3*C

#define SCAN_CHUNK 1024
#define NB_SCAN ((NN + SCAN_CHUNK - 1) / SCAN_CHUNK)   // 49

// GEMM: 3-term bf16 split D = ah*bh + al*bh + ah*bl as 12 pipelined K=32 chunks.
#define TM 128
#define TN 128
#define NCHUNK 12
#define CHUNK_A_BYTES 8192          // 128 rows x 64B
#define BUF_BYTES 16384             // A chunk + B chunk
#define SM_TOT (3 * BUF_BYTES)      // 49152, 3-deep ring -> 2 CTAs/SM

// ---------------- device scratch (no allocations allowed) ----------------
__device__ float g_qkv[NN * QKV_COLS];                        // q,k fp32 (v slots unused)
__device__ __align__(16) __half g_v16[NN * CC];               // fp16 V
__device__ __align__(16) __nv_bfloat16 g_a16[NN * 256];       // [m][hi(128)|lo(128)]
__device__ __align__(16) __nv_bfloat16 g_b16[QKV_COLS * 256];
__device__ __align__(16) float g_pw[NN * HH];                 // per-node per-head coord·w_h
__device__ int   g_offsets[NN + 1];
__device__ int   g_cursor[NN];
__device__ int   g_esrc[EE];
__device__ int   g_bsum[NB_SCAN + 1];
__device__ __align__(16) float g_rpeh[HH * 4];

__device__ __forceinline__ uint32_t smem_to_u32(const void* p) {
    uint32_t a;
    asm("{ .reg .u64 t; cvta.to.shared.u64 t, %1; cvt.u32.u64 %0, t; }" : "=r"(a) : "l"(p));
    return a;
}
#define LDMATRIX_X4(r0, r1, r2, r3, addr) \
    asm volatile("ldmatrix.sync.aligned.m8n8.x4.shared.b16 {%0,%1,%2,%3}, [%4];" \
                 : "=r"(r0), "=r"(r1), "=r"(r2), "=r"(r3) : "r"(addr))
#define MMA_BF16(d, a, b0, b1) \
    asm volatile("mma.sync.aligned.m16n8k16.row.col.f32.bf16.bf16.f32 " \
                 "{%0,%1,%2,%3}, {%4,%5,%6,%7}, {%8,%9}, {%0,%1,%2,%3};" \
                 : "+f"((d)[0]), "+f"((d)[1]), "+f"((d)[2]), "+f"((d)[3]) \
                 : "r"((a)[0]), "r"((a)[1]), "r"((a)[2]), "r"((a)[3]), \
                   "r"(b0), "r"(b1))
#define CP_ASYNC16(smem_addr, gptr, szbytes) \
    asm volatile("cp.async.cg.shared.global [%0], [%1], 16, %2;" \
                 :: "r"(smem_addr), "l"(gptr), "r"(szbytes) : "memory")
#define CP_COMMIT() asm volatile("cp.async.commit_group;" ::: "memory")

__device__ __forceinline__ uint32_t chunk_off(int r, int c) {
    return (uint32_t)((r >> 1) * 128 + (r & 1) * 64 + (((c ^ ((r >> 1) & 3)) & 3) << 4));
}

// ---------------- rpe collapse (main stream) ----------------
__global__ void rpe_kernel(const float* __restrict__ rpe_w,
                           const float* __restrict__ rpe_b) {
    int t = threadIdx.x;
    if (t >= HH * 4) return;
    int h = t >> 2, p = t & 3;
    float s = 0.f;
    for (int d = 0; d < DD; d++) {
        int r = h * DD + d;
        s += (p < 3) ? rpe_w[r * 3 + p] : rpe_b[r];
    }
    g_rpeh[t] = s;
}

// ---------------- per-node per-head coord·w_h ----------------
__global__ void pw_kernel(const float* __restrict__ coord, int n) {
    int idx = blockIdx.x * blockDim.x + threadIdx.x;
    if (idx >= n * HH) return;
    int node = idx >> 2, h = idx & 3;
    float cx = coord[node * 3 + 0];
    float cy = coord[node * 3 + 1];
    float cz = coord[node * 3 + 2];
    float4 w = *reinterpret_cast<const float4*>(&g_rpeh[h * 4]);
    g_pw[idx] = cx * w.x + cy * w.y + cz * w.z;
}

// ---------------- zero degree counters (csr stream) ----------------
__global__ void zero_kernel(int n) {
    int i = blockIdx.x * blockDim.x + threadIdx.x;
    if (i < n) g_cursor[i] = 0;
}

// ---------------- fp32 -> bf16 hi/lo split ----------------
__global__ void conv_a_kernel(const float* __restrict__ feat, int n) {
    int idx = blockIdx.x * blockDim.x + threadIdx.x;
    if (idx >= n * CC) return;
    int m = idx >> 7, k = idx & 127;
    float x = feat[idx];
    __nv_bfloat16 h = __float2bfloat16(x);
    __nv_bfloat16 l = __float2bfloat16(x - __bfloat162float(h));
    g_a16[m * 256 + k] = h;
    g_a16[m * 256 + CC + k] = l;
}
__global__ void conv_b_kernel(const float* __restrict__ w) {
    int idx = blockIdx.x * blockDim.x + threadIdx.x;
    if (idx >= QKV_COLS * CC) return;
    int m = idx >> 7, k = idx & 127;
    float x = w[idx];
    __nv_bfloat16 h = __float2bfloat16(x);
    __nv_bfloat16 l = __float2bfloat16(x - __bfloat162float(h));
    g_b16[m * 256 + k] = h;
    g_b16[m * 256 + CC + k] = l;
}

// ---------------- cp.async-pipelined bf16 3-term split GEMM ----------------
__global__ __launch_bounds__(256, 2)
void mma_gemm_kernel(const float* __restrict__ bias, int M) {
    extern __shared__ char smem[];
    const uint32_t smbase = smem_to_u32(smem);
    const int tid = threadIdx.x;
    const int lane = tid & 31;
    const int wid = tid >> 5;
    const int warpM = wid >> 2;
    const int warpN = wid & 3;
    const int m0 = blockIdx.y * TM;
    const int n0 = blockIdx.x * TN;

    const int aidx[NCHUNK] = {0, 1, 2, 3, 4, 5, 6, 7, 0, 1, 2, 3}; // ah, al, ah
    const int bidx[NCHUNK] = {0, 1, 2, 3, 0, 1, 2, 3, 4, 5, 6, 7}; // bh, bh, bl

    const uint4* a4 = reinterpret_cast<const uint4*>(g_a16);
    const uint4* b4 = reinterpret_cast<const uint4*>(g_b16);

    const int sr0 = tid >> 2, sc0 = tid & 3;
    const int sr1 = (tid + 256) >> 2, sc1 = (tid + 256) & 3;
    const uint32_t soA0 = chunk_off(sr0, sc0), soA1 = chunk_off(sr1, sc1);

    auto ld_chunk = [&](int buf, int ac, int bc) {
        uint32_t base = smbase + (uint32_t)buf * BUF_BYTES;
        int szA0 = (m0 + sr0 < M) ? 16 : 0;
        int szA1 = (m0 + sr1 < M) ? 16 : 0;
        CP_ASYNC16(base + soA0, a4 + (size_t)(m0 + sr0) * 32 + ac * 4 + sc0, szA0);
        CP_ASYNC16(base + soA1, a4 + (size_t)(m0 + sr1) * 32 + ac * 4 + sc1, szA1);
        uint32_t baseB = base + CHUNK_A_BYTES;
        CP_ASYNC16(baseB + soA0, b4 + (size_t)(n0 + sr0) * 32 + bc * 4 + sc0, 16);
        CP_ASYNC16(baseB + soA1, b4 + (size_t)(n0 + sr1) * 32 + bc * 4 + sc1, 16);
        CP_COMMIT();
    };

    float acc[4][4][4];
#pragma unroll
    for (int mt = 0; mt < 4; mt++)
#pragma unroll
        for (int nt = 0; nt < 4; nt++)
#pragma unroll
            for (int c = 0; c < 4; c++) acc[mt][nt][c] = 0.f;

    const int arow_base = warpM * 64 + (lane & 15);
    const int brow_base = warpN * 32 + (lane & 15);
    const int chalf = lane >> 4;

    ld_chunk(0, aidx[0], bidx[0]);
    ld_chunk(1, aidx[1], bidx[1]);

#pragma unroll
    for (int t = 0; t < NCHUNK; t++) {
        if (t < NCHUNK - 1) asm volatile("cp.async.wait_group 1;" ::: "memory");
        else               asm volatile("cp.async.wait_group 0;" ::: "memory");
        __syncthreads();
        if (t + 2 < NCHUNK) ld_chunk((t + 2) % 3, aidx[t + 2], bidx[t + 2]);

        uint32_t bufA = smbase + (uint32_t)(t % 3) * BUF_BYTES;
        uint32_t bufB = bufA + CHUNK_A_BYTES;
#pragma unroll
        for (int ks2 = 0; ks2 < 2; ks2++) {
            int c = ks2 * 2 + chalf;
            uint32_t af[4][4];
#pragma unroll
            for (int mt = 0; mt < 4; mt++) {
                int r = arow_base + mt * 16;
                LDMATRIX_X4(af[mt][0], af[mt][1], af[mt][2], af[mt][3],
                            bufA + chunk_off(r, c));
            }
            uint32_t bf[2][4];
#pragma unroll
            for (int bt = 0; bt < 2; bt++) {
                int r = brow_base + bt * 16;
                LDMATRIX_X4(bf[bt][0], bf[bt][1], bf[bt][2], bf[bt][3],
                            bufB + chunk_off(r, c));
            }
#pragma unroll
            for (int mt = 0; mt < 4; mt++)
#pragma unroll
                for (int nt = 0; nt < 4; nt++) {
                    int bt = nt >> 1, sub = nt & 1;
                    MMA_BF16(acc[mt][nt], af[mt], bf[bt][sub], bf[bt][sub + 2]);
                }
        }
    }

    const int groupID = lane >> 2;
    const int tq = lane & 3;
    const bool is_v = (blockIdx.x == 2);
#pragma unroll
    for (int mt = 0; mt < 4; mt++) {
#pragma unroll
        for (int nt = 0; nt < 4; nt++) {
            int colL = warpN * 32 + nt * 8 + tq * 2;
            int col = n0 + colL;
            float2 b = *reinterpret_cast<const float2*>(&bias[col]);
            int r0 = m0 + warpM * 64 + mt * 16 + groupID;
            int r1 = r0 + 8;
            float2 o0 = make_float2(acc[mt][nt][0] + b.x, acc[mt][nt][1] + b.y);
            float2 o1 = make_float2(acc[mt][nt][2] + b.x, acc[mt][nt][3] + b.y);
            if (is_v) {
                if (r0 < M)
                    *reinterpret_cast<__half2*>(&g_v16[(size_t)r0 * CC + colL]) =
                        __floats2half2_rn(o0.x, o0.y);
                if (r1 < M)
                    *reinterpret_cast<__half2*>(&g_v16[(size_t)r1 * CC + colL]) =
                        __floats2half2_rn(o1.x, o1.y);
            } else {
                if (r0 < M)
                    *reinterpret_cast<float2*>(&g_qkv[(size_t)r0 * QKV_COLS + col]) = o0;
                if (r1 < M)
                    *reinterpret_cast<float2*>(&g_qkv[(size_t)r1 * QKV_COLS + col]) = o1;
            }
        }
    }
}

// ---------------- CSR build ----------------
__global__ void count_kernel(const int* __restrict__ dst, int e) {
    int i = blockIdx.x * blockDim.x + threadIdx.x;
    if (i < e) atomicAdd(&g_cursor[dst[i]], 1);
}

__device__ __forceinline__ int block_scan_inclusive(int v, int* warp_sums) {
    int lane = threadIdx.x & 31;
    int wid  = threadIdx.x >> 5;
    int x = v;
#pragma unroll
    for (int off = 1; off < 32; off <<= 1) {
        int y = __shfl_up_sync(0xffffffffu, x, off);
        if (lane >= off) x += y;
    }
    if (lane == 31) warp_sums[wid] = x;
    __syncthreads();
    if (wid == 0) {
        int ws = warp_sums[lane];
#pragma unroll
        for (int off = 1; off < 32; off <<= 1) {
            int y = __shfl_up_sync(0xffffffffu, ws, off);
            if (lane >= off) ws += y;
        }
        warp_sums[lane] = ws;
    }
    __syncthreads();
    int base = (wid > 0) ? warp_sums[wid - 1] : 0;
    return base + x;
}

__global__ void scan1_kernel(int n) {
    __shared__ int warp_sums[32];
    int i = blockIdx.x * SCAN_CHUNK + threadIdx.x;
    int v = (i < n) ? g_cursor[i] : 0;
    int inc = block_scan_inclusive(v, warp_sums);
    if (i < n) g_offsets[i] = inc - v;
    if (threadIdx.x == SCAN_CHUNK - 1) g_bsum[blockIdx.x] = inc;
}
__global__ void scan2_kernel(int nb) {
    __shared__ int warp_sums[32];
    int v = (threadIdx.x < (unsigned)nb) ? g_bsum[threadIdx.x] : 0;
    int inc = block_scan_inclusive(v, warp_sums);
    if (threadIdx.x < (unsigned)nb) g_bsum[threadIdx.x] = inc - v;
}
__global__ void scan3_kernel(int n, int e) {
    int i = blockIdx.x * SCAN_CHUNK + threadIdx.x;
    if (i < n) {
        int off = g_offsets[i] + g_bsum[blockIdx.x];
        g_offsets[i] = off;
        g_cursor[i]  = off;
    }
    if (i == 0) g_offsets[n] = e;
}
__global__ void fill_kernel(const int* __restrict__ dst,
                            const int* __restrict__ src, int e) {
    int i = blockIdx.x * blockDim.x + threadIdx.x;
    if (i < e) {
        int d = dst[i];
        int pos = atomicAdd(&g_cursor[d], 1);
        g_esrc[pos] = src[i];
    }
}

// ---------------- fused per-node attention (no-max softmax, fp16 V, unroll 4) ----------------
__global__ void attn_kernel(float* __restrict__ out, int n) {
    int warp_in_block = threadIdx.x >> 5;
    int node = blockIdx.x * (blockDim.x >> 5) + warp_in_block;
    if (node >= n) return;
    int lane = threadIdx.x & 31;
    int h = lane >> 3;

    const float bh = g_rpeh[h * 4 + 3];
    const float sd = g_pw[node * HH + h] + bh;     // dst-side rpe term (incl bias)
    const float4 q4 = *reinterpret_cast<const float4*>(&g_qkv[node * QKV_COLS + lane * 4]);

    int beg = g_offsets[node];
    int end = g_offsets[node + 1];

    float lsum = 0.f;
    float4 acc = make_float4(0.f, 0.f, 0.f, 0.f);

    int i = beg;
    for (; i + 3 < end; i += 4) {
        int s0 = g_esrc[i];
        int s1 = g_esrc[i + 1];
        int s2 = g_esrc[i + 2];
        int s3 = g_esrc[i + 3];
        const float4 k0 = *reinterpret_cast<const float4*>(&g_qkv[s0 * QKV_COLS + CC + lane * 4]);
        const float4 k1 = *reinterpret_cast<const float4*>(&g_qkv[s1 * QKV_COLS + CC + lane * 4]);
        const float4 k2 = *reinterpret_cast<const float4*>(&g_qkv[s2 * QKV_COLS + CC + lane * 4]);
        const float4 k3 = *reinterpret_cast<const float4*>(&g_qkv[s3 * QKV_COLS + CC + lane * 4]);
        const uint2 vr0 = *reinterpret_cast<const uint2*>(&g_v16[(size_t)s0 * CC + lane * 4]);
        const uint2 vr1 = *reinterpret_cast<const uint2*>(&g_v16[(size_t)s1 * CC + lane * 4]);
        const uint2 vr2 = *reinterpret_cast<const uint2*>(&g_v16[(size_t)s2 * CC + lane * 4]);
        const uint2 vr3 = *reinterpret_cast<const uint2*>(&g_v16[(size_t)s3 * CC + lane * 4]);
        float ss0 = g_pw[s0 * HH + h];
        float ss1 = g_pw[s1 * HH + h];
        float ss2 = g_pw[s2 * HH + h];
        float ss3 = g_pw[s3 * HH + h];

        float p0 = q4.x * k0.x + q4.y * k0.y + q4.z * k0.z + q4.w * k0.w;
        float p1 = q4.x * k1.x + q4.y * k1.y + q4.z * k1.z + q4.w * k1.w;
        float p2 = q4.x * k2.x + q4.y * k2.y + q4.z * k2.z + q4.w * k2.w;
        float p3 = q4.x * k3.x + q4.y * k3.y + q4.z * k3.z + q4.w * k3.w;
        p0 += __shfl_xor_sync(0xffffffffu, p0, 1);
        p1 += __shfl_xor_sync(0xffffffffu, p1, 1);
        p2 += __shfl_xor_sync(0xffffffffu, p2, 1);
        p3 += __shfl_xor_sync(0xffffffffu, p3, 1);
        p0 += __shfl_xor_sync(0xffffffffu, p0, 2);
        p1 += __shfl_xor_sync(0xffffffffu, p1, 2);
        p2 += __shfl_xor_sync(0xffffffffu, p2, 2);
        p3 += __shfl_xor_sync(0xffffffffu, p3, 2);
        p0 += __shfl_xor_sync(0xffffffffu, p0, 4);
        p1 += __shfl_xor_sync(0xffffffffu, p1, 4);
        p2 += __shfl_xor_sync(0xffffffffu, p2, 4);
        p3 += __shfl_xor_sync(0xffffffffu, p3, 4);

        float e0 = __expf(p0 + sd - ss0);
        float e1 = __expf(p1 + sd - ss1);
        float e2 = __expf(p2 + sd - ss2);
        float e3 = __expf(p3 + sd - ss3);
        lsum += (e0 + e1) + (e2 + e3);

        float2 v0a = __half22float2(*reinterpret_cast<const __half2*>(&vr0.x));
        float2 v0b = __half22float2(*reinterpret_cast<const __half2*>(&vr0.y));
        float2 v1a = __half22float2(*reinterpret_cast<const __half2*>(&vr1.x));
        float2 v1b = __half22float2(*reinterpret_cast<const __half2*>(&vr1.y));
        float2 v2a = __half22float2(*reinterpret_cast<const __half2*>(&vr2.x));
        float2 v2b = __half22float2(*reinterpret_cast<const __half2*>(&vr2.y));
        float2 v3a = __half22float2(*reinterpret_cast<const __half2*>(&vr3.x));
        float2 v3b = __half22float2(*reinterpret_cast<const __half2*>(&vr3.y));
        acc.x += (e0 * v0a.x + e1 * v1a.x) + (e2 * v2a.x + e3 * v3a.x);
        acc.y += (e0 * v0a.y + e1 * v1a.y) + (e2 * v2a.y + e3 * v3a.y);
        acc.z += (e0 * v0b.x + e1 * v1b.x) + (e2 * v2b.x + e3 * v3b.x);
        acc.w += (e0 * v0b.y + e1 * v1b.y) + (e2 * v2b.y + e3 * v3b.y);
    }
    for (; i < end; i++) {
        int s0 = g_esrc[i];
        const float4 k0 = *reinterpret_cast<const float4*>(&g_qkv[s0 * QKV_COLS + CC + lane * 4]);
        const uint2 vr0 = *reinterpret_cast<const uint2*>(&g_v16[(size_t)s0 * CC + lane * 4]);
        float ss0 = g_pw[s0 * HH + h];
        float p0 = q4.x * k0.x + q4.y * k0.y + q4.z * k0.z + q4.w * k0.w;
        p0 += __shfl_xor_sync(0xffffffffu, p0, 1);
        p0 += __shfl_xor_sync(0xffffffffu, p0, 2);
        p0 += __shfl_xor_sync(0xffffffffu, p0, 4);
        float e0 = __expf(p0 + sd - ss0);
        lsum += e0;
        float2 v0a = __half22float2(*reinterpret_cast<const __half2*>(&vr0.x));
        float2 v0b = __half22float2(*reinterpret_cast<const __half2*>(&vr0.y));
        acc.x += e0 * v0a.x;
        acc.y += e0 * v0a.y;
        acc.z += e0 * v0b.x;
        acc.w += e0 * v0b.y;
    }

    float inv = (lsum > 0.f) ? (1.f / lsum) : 0.f;
    float4 r = make_float4(acc.x * inv, acc.y * inv, acc.z * inv, acc.w * inv);
    *reinterpret_cast<float4*>(&out[node * CC + lane * 4]) = r;
}

// ---------------- launch ----------------
extern "C" void kernel_launch(void* const* d_in, const int* in_sizes, int n_in,
                              void* d_out, int out_size) {
    const float* feat   = (const float*)d_in[0];
    const float* coord  = (const float*)d_in[1];
    const int*   graph  = (const int*)d_in[2];
    const float* qkv_w  = (const float*)d_in[3];
    const float* qkv_b  = (const float*)d_in[4];
    const float* rpe_w  = (const float*)d_in[5];
    const float* rpe_b  = (const float*)d_in[6];
    float* out = (float*)d_out;

    int n = in_sizes[0] / CC;      // 50000
    int e = in_sizes[2] / 2;       // 800000
    if (n > NN) n = NN;
    if (e > EE) e = EE;

    const int* dst = graph;
    const int* src = graph + e;

    static cudaStream_t s2 = nullptr;
    static cudaEvent_t evFork = nullptr, evJoin = nullptr;
    if (!s2) {
        cudaStreamCreateWithFlags(&s2, cudaStreamNonBlocking);
        cudaEventCreateWithFlags(&evFork, cudaEventDisableTiming);
        cudaEventCreateWithFlags(&evJoin, cudaEventDisableTiming);
        cudaFuncSetAttribute(mma_gemm_kernel,
                             cudaFuncAttributeMaxDynamicSharedMemorySize, SM_TOT);
    }

    // fork: CSR build chain on s2, GEMM chain on main
    cudaEventRecord(evFork, 0);
    cudaStreamWaitEvent(s2, evFork, 0);

    {   // ---- s2: CSR build by dst ----
        int tb = 256;
        zero_kernel<<<(n + tb - 1) / tb, tb, 0, s2>>>(n);
        count_kernel<<<(e + tb - 1) / tb, tb, 0, s2>>>(dst, e);
        int nb = (n + SCAN_CHUNK - 1) / SCAN_CHUNK;
        scan1_kernel<<<nb, SCAN_CHUNK, 0, s2>>>(n);
        scan2_kernel<<<1, SCAN_CHUNK, 0, s2>>>(nb);
        scan3_kernel<<<nb, SCAN_CHUNK, 0, s2>>>(n, e);
        fill_kernel<<<(e + tb - 1) / tb, tb, 0, s2>>>(dst, src, e);
        cudaEventRecord(evJoin, s2);
    }

    {   // ---- main: rpe + pw + conv + GEMM ----
        rpe_kernel<<<1, 32>>>(rpe_w, rpe_b);
        pw_kernel<<<(n * HH + 255) / 256, 256>>>(coord, n);
        conv_a_kernel<<<(n * CC + 255) / 256, 256>>>(feat, n);
        conv_b_kernel<<<(QKV_COLS * CC + 255) / 256, 256>>>(qkv_w);
        dim3 grid(QKV_COLS / TN, (n + TM - 1) / TM);
        mma_gemm_kernel<<<grid, 256, SM_TOT>>>(qkv_b, n);
    }

    // join, then attention
    cudaStreamWaitEvent(0, evJoin, 0);
    {
        int warps_per_block = 8;
        int tb = warps_per_block * 32;
        int grid = (n + warps_per_block - 1) / warps_per_block;
        attn_kernel<<<grid, tb>>>(out, n);
    }
}